// round 1
// baseline (speedup 1.0000x reference)
#include <cuda_runtime.h>
#include <cuda_bf16.h>
#include <cstdint>

// Problem constants
#define BB    16
#define NN    785            // 1 global + 784 local tokens
#define CC    768
#define HH    12
#define HD    64
#define MROWS (BB * NN)      // 12560
#define QKVN  (3 * CC)       // 2304
#define WXY   28
#define RELW  55             // 2*28-1

// -------- scratch (static device arrays; no allocations allowed) ----------
__device__ float g_q [BB * HH * NN * HD];   // [B,H,N,64], pre-scaled by 1/8
__device__ float g_k [BB * HH * NN * HD];
__device__ float g_v [BB * HH * NN * HD];
__device__ float g_ao[MROWS * CC];          // attention output, [B,N,H*64]

// ---------------------------------------------------------------------------
// NT SGEMM: C[M,N] = A[M,K] * B[N,K]^T   (both row-major)
// 128x128 block tile, BK=16, 256 threads, 8x8 per-thread microtile.
// MODE 0: QKV epilogue -> scatter into g_q/g_k/g_v (Q scaled by 0.125)
// MODE 1: proj epilogue -> Cout[row*N+col] = acc + bias[col]  (A is g_ao)
// ---------------------------------------------------------------------------
template <int MODE>
__global__ void __launch_bounds__(256)
gemm_nt(const float* __restrict__ A, const float* __restrict__ Bm,
        const float* __restrict__ bias, float* __restrict__ Cout,
        int M, int N, int K)
{
    __shared__ float As[16][128];
    __shared__ float Bs[16][128];

    const int tid    = threadIdx.x;
    const int blockM = blockIdx.y * 128;
    const int blockN = blockIdx.x * 128;
    const int tx     = tid & 15;   // N dir
    const int ty     = tid >> 4;   // M dir

    const float* Ap = (MODE == 1) ? g_ao : A;

    float acc[8][8];
#pragma unroll
    for (int i = 0; i < 8; ++i)
#pragma unroll
        for (int j = 0; j < 8; ++j) acc[i][j] = 0.f;

    for (int kt = 0; kt < K; kt += 16) {
        // --- load A tile (128 rows x 16 k), store transposed As[k][m] ---
#pragma unroll
        for (int i = 0; i < 2; ++i) {
            int id = tid + i * 256;           // 0..511
            int r  = id >> 2;
            int kc = (id & 3) * 4;
            float4 v4 = make_float4(0.f, 0.f, 0.f, 0.f);
            int gr = blockM + r;
            if (gr < M)
                v4 = *reinterpret_cast<const float4*>(Ap + (size_t)gr * K + kt + kc);
            As[kc + 0][r] = v4.x; As[kc + 1][r] = v4.y;
            As[kc + 2][r] = v4.z; As[kc + 3][r] = v4.w;
        }
        // --- load B tile (128 cols x 16 k), store Bs[k][n] ---
#pragma unroll
        for (int i = 0; i < 2; ++i) {
            int id = tid + i * 256;
            int c  = id >> 2;
            int kc = (id & 3) * 4;
            float4 v4 = *reinterpret_cast<const float4*>(Bm + (size_t)(blockN + c) * K + kt + kc);
            Bs[kc + 0][c] = v4.x; Bs[kc + 1][c] = v4.y;
            Bs[kc + 2][c] = v4.z; Bs[kc + 3][c] = v4.w;
        }
        __syncthreads();

#pragma unroll
        for (int kk = 0; kk < 16; ++kk) {
            float ra[8], rb[8];
            float4 a0 = *reinterpret_cast<const float4*>(&As[kk][ty * 8]);
            float4 a1 = *reinterpret_cast<const float4*>(&As[kk][ty * 8 + 4]);
            float4 b0 = *reinterpret_cast<const float4*>(&Bs[kk][tx * 8]);
            float4 b1 = *reinterpret_cast<const float4*>(&Bs[kk][tx * 8 + 4]);
            ra[0]=a0.x; ra[1]=a0.y; ra[2]=a0.z; ra[3]=a0.w;
            ra[4]=a1.x; ra[5]=a1.y; ra[6]=a1.z; ra[7]=a1.w;
            rb[0]=b0.x; rb[1]=b0.y; rb[2]=b0.z; rb[3]=b0.w;
            rb[4]=b1.x; rb[5]=b1.y; rb[6]=b1.z; rb[7]=b1.w;
#pragma unroll
            for (int m = 0; m < 8; ++m)
#pragma unroll
                for (int n = 0; n < 8; ++n)
                    acc[m][n] = fmaf(ra[m], rb[n], acc[m][n]);
        }
        __syncthreads();
    }

    // ------------------ epilogue ------------------
#pragma unroll
    for (int m = 0; m < 8; ++m) {
        int row = blockM + ty * 8 + m;
        if (row >= M) continue;
        if (MODE == 0) {
            int b = row / NN;
            int n = row - b * NN;
#pragma unroll
            for (int nn = 0; nn < 8; ++nn) {
                int col = blockN + tx * 8 + nn;
                int s   = col / CC;
                int rem = col - s * CC;
                int h   = rem >> 6;
                int d   = rem & 63;
                float val = acc[m][nn];
                size_t off = (((size_t)b * HH + h) * NN + n) * HD + d;
                if (s == 0)      g_q[off] = val * 0.125f;
                else if (s == 1) g_k[off] = val;
                else             g_v[off] = val;
            }
        } else {
#pragma unroll
            for (int nn = 0; nn < 8; ++nn) {
                int col = blockN + tx * 8 + nn;
                Cout[(size_t)row * N + col] = acc[m][nn] + bias[col];
            }
        }
    }
}

// ---------------------------------------------------------------------------
// Fused attention: one warp per query row, online softmax, bias computed
// analytically per (h, i, j).
// grid: (B*H, ceil(N/8)), block: 256 (8 warps)
// ---------------------------------------------------------------------------
__global__ void __launch_bounds__(256)
attn_kernel(const float* __restrict__ rel_table,
            const float* __restrict__ g2l,
            const float* __restrict__ g2g)
{
    const int bh   = blockIdx.x;                 // b*12 + h
    const int w    = threadIdx.x >> 5;
    const int lane = threadIdx.x & 31;
    const int i    = blockIdx.y * 8 + w;
    if (i >= NN) return;

    const int h = bh % HH;
    const int b = bh / HH;

    const float* qp    = g_q + ((size_t)bh * NN + i) * HD;
    const float2 qv    = *reinterpret_cast<const float2*>(qp + lane * 2);
    const float* kbase = g_k + (size_t)bh * NN * HD;
    const float* vbase = g_v + (size_t)bh * NN * HD;

    // per-row bias parameters
    float bias_j0, bias_glob_row = 0.f;
    int xi = 0, yi = 0;
    if (i == 0) {
        bias_j0       = g2g[h];        // [H,1,1]
        bias_glob_row = g2l[h];        // g2l[0,h,0]
    } else {
        bias_j0 = g2l[HH + h];         // g2l[1,h,0]
        xi = (i - 1) / WXY;
        yi = (i - 1) % WXY;
    }

    float m = -1e30f, l = 0.f;
    float2 acc = make_float2(0.f, 0.f);

    int xj = 0, yj = 0;                // local coords of key j-1
    for (int j = 0; j < NN; ++j) {
        const float2 kv = *reinterpret_cast<const float2*>(kbase + (size_t)j * HD + lane * 2);
        float s = qv.x * kv.x + qv.y * kv.y;
        s += __shfl_xor_sync(0xffffffffu, s, 16);
        s += __shfl_xor_sync(0xffffffffu, s, 8);
        s += __shfl_xor_sync(0xffffffffu, s, 4);
        s += __shfl_xor_sync(0xffffffffu, s, 2);
        s += __shfl_xor_sync(0xffffffffu, s, 1);

        float bias;
        if (j == 0)       bias = bias_j0;
        else if (i == 0)  bias = bias_glob_row;
        else {
            int idx = (xi - xj + (WXY - 1)) * RELW + (yi - yj + (WXY - 1));
            bias = __ldg(rel_table + idx * HH + h);
        }
        s += bias;                     // q already pre-scaled by 1/8

        if (j > 0) { if (++yj == WXY) { yj = 0; ++xj; } }

        const float mnew = fmaxf(m, s);
        const float corr = __expf(m - mnew);
        const float p    = __expf(s - mnew);
        l = l * corr + p;
        const float2 vv = *reinterpret_cast<const float2*>(vbase + (size_t)j * HD + lane * 2);
        acc.x = fmaf(p, vv.x, acc.x * corr);
        acc.y = fmaf(p, vv.y, acc.y * corr);
        m = mnew;
    }

    const float inv = 1.f / l;
    float* op = g_ao + ((size_t)b * NN + i) * CC + h * HD + lane * 2;
    op[0] = acc.x * inv;
    op[1] = acc.y * inv;
}

// ---------------------------------------------------------------------------
extern "C" void kernel_launch(void* const* d_in, const int* in_sizes, int n_in,
                              void* d_out, int out_size)
{
    const float* x         = (const float*)d_in[0];  // [16,785,768]
    const float* qkv_w     = (const float*)d_in[1];  // [2304,768]
    const float* proj_w    = (const float*)d_in[2];  // [768,768]
    const float* proj_b    = (const float*)d_in[3];  // [768]
    const float* rel_table = (const float*)d_in[4];  // [3025,12]
    const float* g2l       = (const float*)d_in[5];  // [2,12,1]
    const float* g2g       = (const float*)d_in[6];  // [12,1,1]
    float* out = (float*)d_out;                      // [16,785,768]

    (void)in_sizes; (void)n_in; (void)out_size;

    // 1) QKV GEMM: [12560,768] x [2304,768]^T -> scattered q/k/v
    {
        dim3 grid(QKVN / 128, (MROWS + 127) / 128);   // (18, 99)
        gemm_nt<0><<<grid, 256>>>(x, qkv_w, nullptr, nullptr, MROWS, QKVN, CC);
    }
    // 2) fused attention -> g_ao
    {
        dim3 grid(BB * HH, (NN + 7) / 8);             // (192, 99)
        attn_kernel<<<grid, 256>>>(rel_table, g2l, g2g);
    }
    // 3) projection GEMM + bias: g_ao[12560,768] x proj_w[768,768]^T -> out
    {
        dim3 grid(CC / 128, (MROWS + 127) / 128);     // (6, 99)
        gemm_nt<1><<<grid, 256>>>(nullptr, proj_w, proj_b, out, MROWS, CC, CC);
    }
}

// round 2
// speedup vs baseline: 3.1123x; 3.1123x over previous
#include <cuda_runtime.h>
#include <cuda_bf16.h>
#include <cstdint>

// Problem constants
#define BB    16
#define NN    785            // 1 global + 784 local tokens
#define CC    768
#define HH    12
#define HD    64
#define MROWS (BB * NN)      // 12560
#define QKVN  (3 * CC)       // 2304
#define WXY   28
#define RELW  55             // 2*28-1

// padded bias dims (rows up to 832 for 13*64 query tiles, stride 836 for float4)
#define BROWS 832
#define BSTR  836

// -------- scratch (static device arrays; no allocations allowed) ----------
__device__ float g_q   [BB * HH * NN * HD];   // [B,H,N,64], pre-scaled by 1/8
__device__ float g_k   [BB * HH * NN * HD];
__device__ float g_v   [BB * HH * NN * HD];
__device__ float g_ao  [MROWS * CC];          // attention output, [B,N,H*64]
__device__ float g_bias[HH * BROWS * BSTR];   // [h][i][j] precomputed bias

// ---------------------------------------------------------------------------
// NT SGEMM: C[M,N] = A[M,K] * B[N,K]^T   (both row-major)
// 128x128 block tile, BK=16, 256 threads, 8x8 per-thread microtile.
// MODE 0: QKV epilogue -> scatter into g_q/g_k/g_v (Q scaled by 0.125)
// MODE 1: proj epilogue -> Cout[row*N+col] = acc + bias[col]  (A is g_ao)
// ---------------------------------------------------------------------------
template <int MODE>
__global__ void __launch_bounds__(256)
gemm_nt(const float* __restrict__ A, const float* __restrict__ Bm,
        const float* __restrict__ bias, float* __restrict__ Cout,
        int M, int N, int K)
{
    __shared__ float As[16][128];
    __shared__ float Bs[16][128];

    const int tid    = threadIdx.x;
    const int blockM = blockIdx.y * 128;
    const int blockN = blockIdx.x * 128;
    const int tx     = tid & 15;   // N dir
    const int ty     = tid >> 4;   // M dir

    const float* Ap = (MODE == 1) ? g_ao : A;

    float acc[8][8];
#pragma unroll
    for (int i = 0; i < 8; ++i)
#pragma unroll
        for (int j = 0; j < 8; ++j) acc[i][j] = 0.f;

    for (int kt = 0; kt < K; kt += 16) {
#pragma unroll
        for (int i = 0; i < 2; ++i) {
            int id = tid + i * 256;
            int r  = id >> 2;
            int kc = (id & 3) * 4;
            float4 v4 = make_float4(0.f, 0.f, 0.f, 0.f);
            int gr = blockM + r;
            if (gr < M)
                v4 = *reinterpret_cast<const float4*>(Ap + (size_t)gr * K + kt + kc);
            As[kc + 0][r] = v4.x; As[kc + 1][r] = v4.y;
            As[kc + 2][r] = v4.z; As[kc + 3][r] = v4.w;
        }
#pragma unroll
        for (int i = 0; i < 2; ++i) {
            int id = tid + i * 256;
            int c  = id >> 2;
            int kc = (id & 3) * 4;
            float4 v4 = *reinterpret_cast<const float4*>(Bm + (size_t)(blockN + c) * K + kt + kc);
            Bs[kc + 0][c] = v4.x; Bs[kc + 1][c] = v4.y;
            Bs[kc + 2][c] = v4.z; Bs[kc + 3][c] = v4.w;
        }
        __syncthreads();

#pragma unroll
        for (int kk = 0; kk < 16; ++kk) {
            float ra[8], rb[8];
            float4 a0 = *reinterpret_cast<const float4*>(&As[kk][ty * 8]);
            float4 a1 = *reinterpret_cast<const float4*>(&As[kk][ty * 8 + 4]);
            float4 b0 = *reinterpret_cast<const float4*>(&Bs[kk][tx * 8]);
            float4 b1 = *reinterpret_cast<const float4*>(&Bs[kk][tx * 8 + 4]);
            ra[0]=a0.x; ra[1]=a0.y; ra[2]=a0.z; ra[3]=a0.w;
            ra[4]=a1.x; ra[5]=a1.y; ra[6]=a1.z; ra[7]=a1.w;
            rb[0]=b0.x; rb[1]=b0.y; rb[2]=b0.z; rb[3]=b0.w;
            rb[4]=b1.x; rb[5]=b1.y; rb[6]=b1.z; rb[7]=b1.w;
#pragma unroll
            for (int m = 0; m < 8; ++m)
#pragma unroll
                for (int n = 0; n < 8; ++n)
                    acc[m][n] = fmaf(ra[m], rb[n], acc[m][n]);
        }
        __syncthreads();
    }

#pragma unroll
    for (int m = 0; m < 8; ++m) {
        int row = blockM + ty * 8 + m;
        if (row >= M) continue;
        if (MODE == 0) {
            int b = row / NN;
            int n = row - b * NN;
#pragma unroll
            for (int nn = 0; nn < 8; ++nn) {
                int col = blockN + tx * 8 + nn;
                int s   = col / CC;
                int rem = col - s * CC;
                int h   = rem >> 6;
                int d   = rem & 63;
                float val = acc[m][nn];
                size_t off = (((size_t)b * HH + h) * NN + n) * HD + d;
                if (s == 0)      g_q[off] = val * 0.125f;
                else if (s == 1) g_k[off] = val;
                else             g_v[off] = val;
            }
        } else {
#pragma unroll
            for (int nn = 0; nn < 8; ++nn) {
                int col = blockN + tx * 8 + nn;
                Cout[(size_t)row * N + col] = acc[m][nn] + bias[col];
            }
        }
    }
}

// ---------------------------------------------------------------------------
// Bias precompute: g_bias[h][i][j]  (i,j < 785; padded region left as-is)
// grid (12, 785), block 256
// ---------------------------------------------------------------------------
__global__ void __launch_bounds__(256)
bias_kernel(const float* __restrict__ rel_table,
            const float* __restrict__ g2l,
            const float* __restrict__ g2g)
{
    const int h = blockIdx.x;
    const int i = blockIdx.y;
    float* row = g_bias + ((size_t)h * BROWS + i) * BSTR;
    const int xi = (i - 1) / WXY, yi = (i - 1) % WXY;
    for (int j = threadIdx.x; j < NN; j += 256) {
        float v;
        if (i == 0)      v = (j == 0) ? g2g[h] : g2l[h];
        else if (j == 0) v = g2l[HH + h];
        else {
            int xj = (j - 1) / WXY, yj = (j - 1) % WXY;
            int idx = (xi - xj + (WXY - 1)) * RELW + (yi - yj + (WXY - 1));
            v = rel_table[idx * HH + h];
        }
        row[j] = v;
    }
}

// ---------------------------------------------------------------------------
// Tiled flash attention: block = 64 queries of one (b,h); key tiles of 64.
// 256 threads, 4x4 microtiles for both S=QK^T and O+=PV GEMMs.
// dyn smem: Qs[64][64](d-major) Ks[64][64](d-major) Vs[64][68] Ps[64][68]
// ---------------------------------------------------------------------------
#define ATTN_SMEM ((4096 + 4096 + 64*68 + 64*68) * 4)

__global__ void __launch_bounds__(256)
attn_tiled()
{
    extern __shared__ float sm[];
    float* Qs = sm;                 // Qs[d*64 + i]
    float* Ks = Qs + 4096;          // Ks[d*64 + j]
    float* Vs = Ks + 4096;          // Vs[j*68 + d]
    float* Ps = Vs + 64 * 68;       // Ps[i*68 + j]

    const int bh = blockIdx.y;
    const int b  = bh / HH;
    const int h  = bh - b * HH;
    const int q0 = blockIdx.x * 64;

    const int tid = threadIdx.x;
    const int tx  = tid & 15;       // covers 4 cols (key j / dim d)
    const int ty  = tid >> 4;       // covers 4 rows (query i)
    const int jl  = tid & 63;       // row index for tile loads
    const int dsl = (tid >> 6) * 16;// d-slice base for tile loads

    const float* Qg = g_q + (size_t)bh * NN * HD;
    const float* Kg = g_k + (size_t)bh * NN * HD;
    const float* Vg = g_v + (size_t)bh * NN * HD;
    const float* Bh = g_bias + (size_t)h * BROWS * BSTR;

    // ---- load Q tile (transposed to d-major) ----
    {
        const int i = q0 + jl;
        const bool inb = i < NN;
#pragma unroll
        for (int u = 0; u < 4; ++u) {
            const int d0 = dsl + u * 4;
            float4 v = make_float4(0.f, 0.f, 0.f, 0.f);
            if (inb) v = *reinterpret_cast<const float4*>(Qg + (size_t)i * HD + d0);
            Qs[(d0 + 0) * 64 + jl] = v.x;
            Qs[(d0 + 1) * 64 + jl] = v.y;
            Qs[(d0 + 2) * 64 + jl] = v.z;
            Qs[(d0 + 3) * 64 + jl] = v.w;
        }
    }

    float o[4][4];
    float l[4], mrow[4];
#pragma unroll
    for (int m = 0; m < 4; ++m) {
        l[m] = 0.f; mrow[m] = -1e30f;
#pragma unroll
        for (int n = 0; n < 4; ++n) o[m][n] = 0.f;
    }

    for (int kt = 0; kt < 13; ++kt) {
        const int k0 = kt * 64;
        __syncthreads();   // everyone done reading Vs/Ps of prev iter

        // ---- load K (d-major) and V (natural) tiles ----
        {
            const int j = k0 + jl;
            const bool inb = j < NN;
#pragma unroll
            for (int u = 0; u < 4; ++u) {
                const int d0 = dsl + u * 4;
                float4 kv = make_float4(0.f, 0.f, 0.f, 0.f);
                float4 vv = make_float4(0.f, 0.f, 0.f, 0.f);
                if (inb) {
                    kv = *reinterpret_cast<const float4*>(Kg + (size_t)j * HD + d0);
                    vv = *reinterpret_cast<const float4*>(Vg + (size_t)j * HD + d0);
                }
                Ks[(d0 + 0) * 64 + jl] = kv.x;
                Ks[(d0 + 1) * 64 + jl] = kv.y;
                Ks[(d0 + 2) * 64 + jl] = kv.z;
                Ks[(d0 + 3) * 64 + jl] = kv.w;
                *reinterpret_cast<float4*>(Vs + jl * 68 + d0) = vv;
            }
        }
        __syncthreads();

        // ---- S = Q K^T (64x64x64) ----
        float s[4][4];
#pragma unroll
        for (int m = 0; m < 4; ++m)
#pragma unroll
            for (int n = 0; n < 4; ++n) s[m][n] = 0.f;

#pragma unroll 8
        for (int kk = 0; kk < 64; ++kk) {
            const float4 qa = *reinterpret_cast<const float4*>(Qs + kk * 64 + ty * 4);
            const float4 kb = *reinterpret_cast<const float4*>(Ks + kk * 64 + tx * 4);
            const float ra[4] = {qa.x, qa.y, qa.z, qa.w};
            const float rb[4] = {kb.x, kb.y, kb.z, kb.w};
#pragma unroll
            for (int m = 0; m < 4; ++m)
#pragma unroll
                for (int n = 0; n < 4; ++n)
                    s[m][n] = fmaf(ra[m], rb[n], s[m][n]);
        }

        // ---- bias + OOB mask ----
#pragma unroll
        for (int m = 0; m < 4; ++m) {
            const int i = q0 + ty * 4 + m;     // < 832 always: in padded bias
            const float4 bb = *reinterpret_cast<const float4*>(
                Bh + (size_t)i * BSTR + k0 + tx * 4);
            s[m][0] += bb.x; s[m][1] += bb.y; s[m][2] += bb.z; s[m][3] += bb.w;
        }
        if (k0 + 64 > NN) {
#pragma unroll
            for (int n = 0; n < 4; ++n)
                if (k0 + tx * 4 + n >= NN) {
#pragma unroll
                    for (int m = 0; m < 4; ++m) s[m][n] = -1e30f;
                }
        }

        // ---- online softmax update ----
#pragma unroll
        for (int m = 0; m < 4; ++m) {
            float mx = fmaxf(fmaxf(s[m][0], s[m][1]), fmaxf(s[m][2], s[m][3]));
            mx = fmaxf(mx, __shfl_xor_sync(0xffffffffu, mx, 1, 16));
            mx = fmaxf(mx, __shfl_xor_sync(0xffffffffu, mx, 2, 16));
            mx = fmaxf(mx, __shfl_xor_sync(0xffffffffu, mx, 4, 16));
            mx = fmaxf(mx, __shfl_xor_sync(0xffffffffu, mx, 8, 16));
            const float mnew = fmaxf(mrow[m], mx);
            const float corr = __expf(mrow[m] - mnew);
            mrow[m] = mnew;
            float ps = 0.f;
#pragma unroll
            for (int n = 0; n < 4; ++n) {
                s[m][n] = __expf(s[m][n] - mnew);
                ps += s[m][n];
            }
            ps += __shfl_xor_sync(0xffffffffu, ps, 1, 16);
            ps += __shfl_xor_sync(0xffffffffu, ps, 2, 16);
            ps += __shfl_xor_sync(0xffffffffu, ps, 4, 16);
            ps += __shfl_xor_sync(0xffffffffu, ps, 8, 16);
            l[m] = l[m] * corr + ps;
#pragma unroll
            for (int n = 0; n < 4; ++n) o[m][n] *= corr;
        }

        // ---- stage P to smem (natural [i][j], float4 rows) ----
#pragma unroll
        for (int m = 0; m < 4; ++m) {
            *reinterpret_cast<float4*>(Ps + (ty * 4 + m) * 68 + tx * 4) =
                make_float4(s[m][0], s[m][1], s[m][2], s[m][3]);
        }
        __syncthreads();

        // ---- O += P V (64x64x64) ----
#pragma unroll 8
        for (int kk = 0; kk < 64; ++kk) {
            const float4 vb = *reinterpret_cast<const float4*>(Vs + kk * 68 + tx * 4);
            const float rb[4] = {vb.x, vb.y, vb.z, vb.w};
            float ra[4];
#pragma unroll
            for (int m = 0; m < 4; ++m) ra[m] = Ps[(ty * 4 + m) * 68 + kk];
#pragma unroll
            for (int m = 0; m < 4; ++m)
#pragma unroll
                for (int n = 0; n < 4; ++n)
                    o[m][n] = fmaf(ra[m], rb[n], o[m][n]);
        }
    }

    // ---- normalize + write [B,N,H*64] ----
#pragma unroll
    for (int m = 0; m < 4; ++m) {
        const int i = q0 + ty * 4 + m;
        if (i < NN) {
            const float inv = 1.f / l[m];
            *reinterpret_cast<float4*>(
                g_ao + ((size_t)b * NN + i) * CC + h * HD + tx * 4) =
                make_float4(o[m][0] * inv, o[m][1] * inv, o[m][2] * inv, o[m][3] * inv);
        }
    }
}

// ---------------------------------------------------------------------------
extern "C" void kernel_launch(void* const* d_in, const int* in_sizes, int n_in,
                              void* d_out, int out_size)
{
    const float* x         = (const float*)d_in[0];  // [16,785,768]
    const float* qkv_w     = (const float*)d_in[1];  // [2304,768]
    const float* proj_w    = (const float*)d_in[2];  // [768,768]
    const float* proj_b    = (const float*)d_in[3];  // [768]
    const float* rel_table = (const float*)d_in[4];  // [3025,12]
    const float* g2l       = (const float*)d_in[5];  // [2,12,1]
    const float* g2g       = (const float*)d_in[6];  // [12,1,1]
    float* out = (float*)d_out;                      // [16,785,768]

    (void)in_sizes; (void)n_in; (void)out_size;

    cudaFuncSetAttribute(attn_tiled,
                         cudaFuncAttributeMaxDynamicSharedMemorySize, ATTN_SMEM);

    // 0) bias precompute
    {
        dim3 grid(HH, NN);
        bias_kernel<<<grid, 256>>>(rel_table, g2l, g2g);
    }
    // 1) QKV GEMM: [12560,768] x [2304,768]^T -> scattered q/k/v
    {
        dim3 grid(QKVN / 128, (MROWS + 127) / 128);   // (18, 99)
        gemm_nt<0><<<grid, 256>>>(x, qkv_w, nullptr, nullptr, MROWS, QKVN, CC);
    }
    // 2) tiled flash attention -> g_ao
    {
        dim3 grid(13, BB * HH);                       // (13, 192)
        attn_tiled<<<grid, 256, ATTN_SMEM>>>();
    }
    // 3) projection GEMM + bias: g_ao[12560,768] x proj_w[768,768]^T -> out
    {
        dim3 grid(CC / 128, (MROWS + 127) / 128);     // (6, 99)
        gemm_nt<1><<<grid, 256>>>(nullptr, proj_w, proj_b, out, MROWS, CC, CC);
    }
}

// round 4
// speedup vs baseline: 5.0279x; 1.6155x over previous
#include <cuda_runtime.h>
#include <cuda_bf16.h>
#include <cstdint>

// Problem constants
#define BB    16
#define NN    785
#define CC    768
#define HH    12
#define HD    64
#define MROWS (BB * NN)      // 12560
#define QKVN  (3 * CC)       // 2304
#define WXY   28
#define RELW  55
#define BROWS 832
#define BSTR  836
#define KDIM  768
#define NCHUNK 24            // 768 / 32

// -------- scratch (static device arrays; no allocations allowed) ----------
__device__ float g_x32[MROWS * CC];          // x rounded to tf32
__device__ float g_wq [QKVN * CC];           // qkv_w rounded to tf32
__device__ float g_wp [CC * CC];             // proj_w rounded to tf32
__device__ float g_q  [BB * HH * NN * HD];   // [B,H,N,64], Q pre-scaled 1/8
__device__ float g_k  [BB * HH * NN * HD];
__device__ float g_v  [BB * HH * NN * HD];
__device__ float g_ao [MROWS * CC];          // attention out (tf32-rounded)
__device__ float g_bias[HH * BROWS * BSTR];  // [h][i][j] bias

// ---------------------------------------------------------------------------
__device__ __forceinline__ uint32_t smem_u32(const void* p) {
    uint32_t a;
    asm("{ .reg .u64 t; cvta.to.shared.u64 t, %1; cvt.u32.u64 %0, t; }"
        : "=r"(a) : "l"(p));
    return a;
}
__device__ __forceinline__ float rna_tf32(float v) {
    uint32_t u;
    asm("cvt.rna.tf32.f32 %0, %1;" : "=r"(u) : "f"(v));
    return __uint_as_float(u);
}
__device__ __forceinline__ void mma_tf32(float* d, const uint32_t* a,
                                         const uint32_t* b) {
    asm volatile(
        "mma.sync.aligned.m16n8k8.row.col.f32.tf32.tf32.f32 "
        "{%0,%1,%2,%3}, {%4,%5,%6,%7}, {%8,%9}, {%0,%1,%2,%3};"
        : "+f"(d[0]), "+f"(d[1]), "+f"(d[2]), "+f"(d[3])
        : "r"(a[0]), "r"(a[1]), "r"(a[2]), "r"(a[3]), "r"(b[0]), "r"(b[1]));
}

// ---------------------------------------------------------------------------
// tf32 rounding pre-pass.  MODE: 0 -> g_x32, 1 -> g_wq, 2 -> g_wp
// ---------------------------------------------------------------------------
template <int MODE>
__global__ void __launch_bounds__(256)
round_tf32(const float* __restrict__ src, int n4)
{
    float* dst = (MODE == 0) ? g_x32 : (MODE == 1) ? g_wq : g_wp;
    int i = blockIdx.x * 256 + threadIdx.x;
    if (i < n4) {
        float4 v = reinterpret_cast<const float4*>(src)[i];
        v.x = rna_tf32(v.x); v.y = rna_tf32(v.y);
        v.z = rna_tf32(v.z); v.w = rna_tf32(v.w);
        reinterpret_cast<float4*>(dst)[i] = v;
    }
}

// ---------------------------------------------------------------------------
// tf32 mma.sync NT GEMM: C[M,n] = A[M,768] * B[n,768]^T
// 128x128 CTA tile, BK=32, 2-stage cp.async, 8 warps in 4(M)x2(N),
// warp tile 32x64 via m16n8k8 fragments.
// Smem per stage: As[128][36] + Bs[128][36] floats; stride 36 -> conflict-free.
// MODE 0: A=g_x32, B=g_wq, epilogue scatters q/k/v (Q * 0.125)
// MODE 1: A=g_ao,  B=g_wp, epilogue adds bias -> Cout
// ---------------------------------------------------------------------------
#define ASTRIDE   36
#define ABLK_F    (128 * ASTRIDE)        // 4608 floats
#define STAGE_F   (2 * ABLK_F)           // 9216 floats (A + B)
#define GEMM_SMEM (2 * STAGE_F * 4)      // 73728 bytes

template <int MODE>
__global__ void __launch_bounds__(256)
gemm_mma(const float* __restrict__ bias, float* __restrict__ Cout, int M)
{
    extern __shared__ float sm[];
    const uint32_t sbase = smem_u32(sm);

    const float* __restrict__ A  = (MODE == 0) ? g_x32 : g_ao;
    const float* __restrict__ Bm = (MODE == 0) ? g_wq  : g_wp;

    const int tid    = threadIdx.x;
    const int blockM = blockIdx.y * 128;
    const int blockN = blockIdx.x * 128;

    // ---- global -> smem mapping: row = tid>>1, half(16 floats) = tid&1 ----
    const int lrow  = tid >> 1;
    const int lhalf = tid & 1;
    const int arow  = blockM + lrow;
    const bool aok  = arow < M;
    const float* aptr = A  + (size_t)(aok ? arow : 0) * KDIM + lhalf * 16;
    const float* bptr = Bm + (size_t)(blockN + lrow) * KDIM + lhalf * 16;
    const uint32_t adst = sbase + (uint32_t)(lrow * ASTRIDE + lhalf * 16) * 4;
    const uint32_t bdst = adst + ABLK_F * 4;
    const int asz = aok ? 16 : 0;

#define LOADC(c) do {                                                          \
        uint32_t _so = ((c) & 1) * (STAGE_F * 4);                              \
        const float* _as = aptr + (c) * 32;                                    \
        const float* _bs = bptr + (c) * 32;                                    \
        _Pragma("unroll")                                                      \
        for (int _i = 0; _i < 4; ++_i)                                         \
            asm volatile("cp.async.cg.shared.global [%0], [%1], 16, %2;"       \
                :: "r"(adst + _so + _i * 16), "l"(_as + _i * 4), "r"(asz));    \
        _Pragma("unroll")                                                      \
        for (int _i = 0; _i < 4; ++_i)                                         \
            asm volatile("cp.async.cg.shared.global [%0], [%1], 16, 16;"       \
                :: "r"(bdst + _so + _i * 16), "l"(_bs + _i * 4));              \
        asm volatile("cp.async.commit_group;");                                \
    } while (0)

    const int lane  = tid & 31;
    const int wid   = tid >> 5;
    const int warpM = (wid & 3) * 32;
    const int warpN = (wid >> 2) * 64;
    const int tq    = lane >> 2;   // group id (row within fragment)
    const int tr    = lane & 3;    // thread-in-group (k / col pair)

    float acc[2][8][4];
#pragma unroll
    for (int mt = 0; mt < 2; ++mt)
#pragma unroll
        for (int nt = 0; nt < 8; ++nt)
#pragma unroll
            for (int e = 0; e < 4; ++e) acc[mt][nt][e] = 0.f;

    LOADC(0);

    for (int c = 0; c < NCHUNK; ++c) {
        if (c + 1 < NCHUNK) {
            LOADC(c + 1);
            asm volatile("cp.async.wait_group 1;");
        } else {
            asm volatile("cp.async.wait_group 0;");
        }
        __syncthreads();

        const float* As = sm + (c & 1) * STAGE_F;
        const float* Bs = As + ABLK_F;

#pragma unroll
        for (int ks = 0; ks < 4; ++ks) {
            const int k0 = ks * 8;
            uint32_t af[2][4];
#pragma unroll
            for (int mt = 0; mt < 2; ++mt) {
                const float* ap = As + (warpM + mt * 16 + tq) * ASTRIDE + k0 + tr;
                af[mt][0] = __float_as_uint(ap[0]);
                af[mt][1] = __float_as_uint(ap[8 * ASTRIDE]);
                af[mt][2] = __float_as_uint(ap[4]);
                af[mt][3] = __float_as_uint(ap[8 * ASTRIDE + 4]);
            }
#pragma unroll
            for (int nt = 0; nt < 8; ++nt) {
                const float* bp = Bs + (warpN + nt * 8 + tq) * ASTRIDE + k0 + tr;
                uint32_t bf[2] = { __float_as_uint(bp[0]), __float_as_uint(bp[4]) };
#pragma unroll
                for (int mt = 0; mt < 2; ++mt)
                    mma_tf32(acc[mt][nt], af[mt], bf);
            }
        }
        __syncthreads();
    }
#undef LOADC

    // ---- epilogue ----
#pragma unroll
    for (int mt = 0; mt < 2; ++mt) {
#pragma unroll
        for (int half = 0; half < 2; ++half) {
            const int row = blockM + warpM + mt * 16 + tq + half * 8;
            if (row >= M) continue;
            int b = 0, n = 0;
            if (MODE == 0) { b = row / NN; n = row - b * NN; }
#pragma unroll
            for (int nt = 0; nt < 8; ++nt) {
                const int col = blockN + warpN + nt * 8 + tr * 2;
                const float vx = acc[mt][nt][half * 2 + 0];
                const float vy = acc[mt][nt][half * 2 + 1];
                if (MODE == 0) {
                    const int s   = col / CC;
                    const int rem = col - s * CC;
                    const int h   = rem >> 6;
                    const int d   = rem & 63;
                    const float scl = (s == 0) ? 0.125f : 1.f;
                    float* dp = (s == 0 ? g_q : (s == 1 ? g_k : g_v)) +
                                (((size_t)b * HH + h) * NN + n) * HD + d;
                    *reinterpret_cast<float2*>(dp) = make_float2(vx * scl, vy * scl);
                } else {
                    *reinterpret_cast<float2*>(Cout + (size_t)row * CC + col) =
                        make_float2(vx + bias[col], vy + bias[col + 1]);
                }
            }
        }
    }
}

// ---------------------------------------------------------------------------
// Bias precompute
// ---------------------------------------------------------------------------
__global__ void __launch_bounds__(256)
bias_kernel(const float* __restrict__ rel_table,
            const float* __restrict__ g2l,
            const float* __restrict__ g2g)
{
    const int h = blockIdx.x;
    const int i = blockIdx.y;
    float* row = g_bias + ((size_t)h * BROWS + i) * BSTR;
    const int xi = (i - 1) / WXY, yi = (i - 1) % WXY;
    for (int j = threadIdx.x; j < NN; j += 256) {
        float v;
        if (i == 0)      v = (j == 0) ? g2g[h] : g2l[h];
        else if (j == 0) v = g2l[HH + h];
        else {
            int xj = (j - 1) / WXY, yj = (j - 1) % WXY;
            int idx = (xi - xj + (WXY - 1)) * RELW + (yi - yj + (WXY - 1));
            v = rel_table[idx * HH + h];
        }
        row[j] = v;
    }
}

// ---------------------------------------------------------------------------
// Tiled flash attention (verified SIMT version; writes tf32-rounded g_ao)
// ---------------------------------------------------------------------------
#define ATTN_SMEM ((4096 + 4096 + 64*68 + 64*68) * 4)

__global__ void __launch_bounds__(256)
attn_tiled()
{
    extern __shared__ float sm[];
    float* Qs = sm;
    float* Ks = Qs + 4096;
    float* Vs = Ks + 4096;
    float* Ps = Vs + 64 * 68;

    const int bh = blockIdx.y;
    const int b  = bh / HH;
    const int h  = bh - b * HH;
    const int q0 = blockIdx.x * 64;

    const int tid = threadIdx.x;
    const int tx  = tid & 15;
    const int ty  = tid >> 4;
    const int jl  = tid & 63;
    const int dsl = (tid >> 6) * 16;

    const float* Qg = g_q + (size_t)bh * NN * HD;
    const float* Kg = g_k + (size_t)bh * NN * HD;
    const float* Vg = g_v + (size_t)bh * NN * HD;
    const float* Bh = g_bias + (size_t)h * BROWS * BSTR;

    {
        const int i = q0 + jl;
        const bool inb = i < NN;
#pragma unroll
        for (int u = 0; u < 4; ++u) {
            const int d0 = dsl + u * 4;
            float4 v = make_float4(0.f, 0.f, 0.f, 0.f);
            if (inb) v = *reinterpret_cast<const float4*>(Qg + (size_t)i * HD + d0);
            Qs[(d0 + 0) * 64 + jl] = v.x;
            Qs[(d0 + 1) * 64 + jl] = v.y;
            Qs[(d0 + 2) * 64 + jl] = v.z;
            Qs[(d0 + 3) * 64 + jl] = v.w;
        }
    }

    float o[4][4];
    float l[4], mrow[4];
#pragma unroll
    for (int m = 0; m < 4; ++m) {
        l[m] = 0.f; mrow[m] = -1e30f;
#pragma unroll
        for (int n = 0; n < 4; ++n) o[m][n] = 0.f;
    }

    for (int kt = 0; kt < 13; ++kt) {
        const int k0 = kt * 64;
        __syncthreads();
        {
            const int j = k0 + jl;
            const bool inb = j < NN;
#pragma unroll
            for (int u = 0; u < 4; ++u) {
                const int d0 = dsl + u * 4;
                float4 kv = make_float4(0.f, 0.f, 0.f, 0.f);
                float4 vv = make_float4(0.f, 0.f, 0.f, 0.f);
                if (inb) {
                    kv = *reinterpret_cast<const float4*>(Kg + (size_t)j * HD + d0);
                    vv = *reinterpret_cast<const float4*>(Vg + (size_t)j * HD + d0);
                }
                Ks[(d0 + 0) * 64 + jl] = kv.x;
                Ks[(d0 + 1) * 64 + jl] = kv.y;
                Ks[(d0 + 2) * 64 + jl] = kv.z;
                Ks[(d0 + 3) * 64 + jl] = kv.w;
                *reinterpret_cast<float4*>(Vs + jl * 68 + d0) = vv;
            }
        }
        __syncthreads();

        float s[4][4];
#pragma unroll
        for (int m = 0; m < 4; ++m)
#pragma unroll
            for (int n = 0; n < 4; ++n) s[m][n] = 0.f;

#pragma unroll 8
        for (int kk = 0; kk < 64; ++kk) {
            const float4 qa = *reinterpret_cast<const float4*>(Qs + kk * 64 + ty * 4);
            const float4 kb = *reinterpret_cast<const float4*>(Ks + kk * 64 + tx * 4);
            const float ra[4] = {qa.x, qa.y, qa.z, qa.w};
            const float rb[4] = {kb.x, kb.y, kb.z, kb.w};
#pragma unroll
            for (int m = 0; m < 4; ++m)
#pragma unroll
                for (int n = 0; n < 4; ++n)
                    s[m][n] = fmaf(ra[m], rb[n], s[m][n]);
        }

#pragma unroll
        for (int m = 0; m < 4; ++m) {
            const int i = q0 + ty * 4 + m;
            const float4 bb = *reinterpret_cast<const float4*>(
                Bh + (size_t)i * BSTR + k0 + tx * 4);
            s[m][0] += bb.x; s[m][1] += bb.y; s[m][2] += bb.z; s[m][3] += bb.w;
        }
        if (k0 + 64 > NN) {
#pragma unroll
            for (int n = 0; n < 4; ++n)
                if (k0 + tx * 4 + n >= NN) {
#pragma unroll
                    for (int m = 0; m < 4; ++m) s[m][n] = -1e30f;
                }
        }

#pragma unroll
        for (int m = 0; m < 4; ++m) {
            float mx = fmaxf(fmaxf(s[m][0], s[m][1]), fmaxf(s[m][2], s[m][3]));
            mx = fmaxf(mx, __shfl_xor_sync(0xffffffffu, mx, 1, 16));
            mx = fmaxf(mx, __shfl_xor_sync(0xffffffffu, mx, 2, 16));
            mx = fmaxf(mx, __shfl_xor_sync(0xffffffffu, mx, 4, 16));
            mx = fmaxf(mx, __shfl_xor_sync(0xffffffffu, mx, 8, 16));
            const float mnew = fmaxf(mrow[m], mx);
            const float corr = __expf(mrow[m] - mnew);
            mrow[m] = mnew;
            float ps = 0.f;
#pragma unroll
            for (int n = 0; n < 4; ++n) {
                s[m][n] = __expf(s[m][n] - mnew);
                ps += s[m][n];
            }
            ps += __shfl_xor_sync(0xffffffffu, ps, 1, 16);
            ps += __shfl_xor_sync(0xffffffffu, ps, 2, 16);
            ps += __shfl_xor_sync(0xffffffffu, ps, 4, 16);
            ps += __shfl_xor_sync(0xffffffffu, ps, 8, 16);
            l[m] = l[m] * corr + ps;
#pragma unroll
            for (int n = 0; n < 4; ++n) o[m][n] *= corr;
        }

#pragma unroll
        for (int m = 0; m < 4; ++m) {
            *reinterpret_cast<float4*>(Ps + (ty * 4 + m) * 68 + tx * 4) =
                make_float4(s[m][0], s[m][1], s[m][2], s[m][3]);
        }
        __syncthreads();

#pragma unroll 8
        for (int kk = 0; kk < 64; ++kk) {
            const float4 vb = *reinterpret_cast<const float4*>(Vs + kk * 68 + tx * 4);
            const float rb[4] = {vb.x, vb.y, vb.z, vb.w};
            float ra[4];
#pragma unroll
            for (int m = 0; m < 4; ++m) ra[m] = Ps[(ty * 4 + m) * 68 + kk];
#pragma unroll
            for (int m = 0; m < 4; ++m)
#pragma unroll
                for (int n = 0; n < 4; ++n)
                    o[m][n] = fmaf(ra[m], rb[n], o[m][n]);
        }
    }

#pragma unroll
    for (int m = 0; m < 4; ++m) {
        const int i = q0 + ty * 4 + m;
        if (i < NN) {
            const float inv = 1.f / l[m];
            float4 w = make_float4(o[m][0] * inv, o[m][1] * inv,
                                   o[m][2] * inv, o[m][3] * inv);
            w.x = rna_tf32(w.x); w.y = rna_tf32(w.y);
            w.z = rna_tf32(w.z); w.w = rna_tf32(w.w);
            *reinterpret_cast<float4*>(
                g_ao + ((size_t)b * NN + i) * CC + h * HD + tx * 4) = w;
        }
    }
}

// ---------------------------------------------------------------------------
extern "C" void kernel_launch(void* const* d_in, const int* in_sizes, int n_in,
                              void* d_out, int out_size)
{
    const float* x         = (const float*)d_in[0];
    const float* qkv_w     = (const float*)d_in[1];
    const float* proj_w    = (const float*)d_in[2];
    const float* proj_b    = (const float*)d_in[3];
    const float* rel_table = (const float*)d_in[4];
    const float* g2l       = (const float*)d_in[5];
    const float* g2g       = (const float*)d_in[6];
    float* out = (float*)d_out;

    (void)in_sizes; (void)n_in; (void)out_size;

    cudaFuncSetAttribute(attn_tiled,
                         cudaFuncAttributeMaxDynamicSharedMemorySize, ATTN_SMEM);
    cudaFuncSetAttribute(gemm_mma<0>,
                         cudaFuncAttributeMaxDynamicSharedMemorySize, GEMM_SMEM);
    cudaFuncSetAttribute(gemm_mma<1>,
                         cudaFuncAttributeMaxDynamicSharedMemorySize, GEMM_SMEM);

    // 0) tf32 rounding pre-passes + bias precompute
    {
        int n4x = MROWS * CC / 4, n4q = QKVN * CC / 4, n4p = CC * CC / 4;
        round_tf32<0><<<(n4x + 255) / 256, 256>>>(x, n4x);
        round_tf32<1><<<(n4q + 255) / 256, 256>>>(qkv_w, n4q);
        round_tf32<2><<<(n4p + 255) / 256, 256>>>(proj_w, n4p);
        dim3 gb(HH, NN);
        bias_kernel<<<gb, 256>>>(rel_table, g2l, g2g);
    }
    // 1) QKV GEMM (tf32 mma.sync): [12560,768] x [2304,768]^T -> q/k/v
    {
        dim3 grid(QKVN / 128, (MROWS + 127) / 128);   // (18, 99)
        gemm_mma<0><<<grid, 256, GEMM_SMEM>>>(nullptr, nullptr, MROWS);
    }
    // 2) tiled flash attention -> g_ao
    {
        dim3 grid(13, BB * HH);
        attn_tiled<<<grid, 256, ATTN_SMEM>>>();
    }
    // 3) proj GEMM (tf32 mma.sync) + bias -> out
    {
        dim3 grid(CC / 128, (MROWS + 127) / 128);     // (6, 99)
        gemm_mma<1><<<grid, 256, GEMM_SMEM>>>(proj_b, out, MROWS);
    }
}

// round 5
// speedup vs baseline: 8.6950x; 1.7293x over previous
#include <cuda_runtime.h>
#include <cuda_bf16.h>
#include <cstdint>

// Problem constants
#define BB    16
#define NN    785
#define CC    768
#define HH    12
#define HD    64
#define MROWS (BB * NN)      // 12560
#define QKVN  (3 * CC)       // 2304
#define WXY   28
#define RELW  55
#define BROWS 896            // padded query rows for bias (7 * 128)
#define BSTR  836
#define KDIM  768
#define NCHUNK 24            // 768 / 32

// -------- scratch (static device arrays; no allocations allowed) ----------
__device__ float g_x32[MROWS * CC];          // x rounded to tf32
__device__ float g_wq [QKVN * CC];           // qkv_w rounded to tf32
__device__ float g_wp [CC * CC];             // proj_w rounded to tf32
__device__ float g_q  [BB * HH * NN * HD];   // [B,H,N,64], Q pre-scaled 1/8
__device__ float g_k  [BB * HH * NN * HD];
__device__ float g_v  [BB * HH * NN * HD];
__device__ float g_ao [MROWS * CC];          // attention out (tf32-rounded)
__device__ float g_bias[HH * BROWS * BSTR];  // [h][i][j] bias (pad rows stay 0)

// ---------------------------------------------------------------------------
__device__ __forceinline__ uint32_t smem_u32(const void* p) {
    uint32_t a;
    asm("{ .reg .u64 t; cvta.to.shared.u64 t, %1; cvt.u32.u64 %0, t; }"
        : "=r"(a) : "l"(p));
    return a;
}
__device__ __forceinline__ float rna_tf32(float v) {
    uint32_t u;
    asm("cvt.rna.tf32.f32 %0, %1;" : "=r"(u) : "f"(v));
    return __uint_as_float(u);
}
__device__ __forceinline__ void mma_tf32(float* d, const uint32_t* a,
                                         const uint32_t* b) {
    asm volatile(
        "mma.sync.aligned.m16n8k8.row.col.f32.tf32.tf32.f32 "
        "{%0,%1,%2,%3}, {%4,%5,%6,%7}, {%8,%9}, {%0,%1,%2,%3};"
        : "+f"(d[0]), "+f"(d[1]), "+f"(d[2]), "+f"(d[3])
        : "r"(a[0]), "r"(a[1]), "r"(a[2]), "r"(a[3]), "r"(b[0]), "r"(b[1]));
}

// ---------------------------------------------------------------------------
// tf32 rounding pre-pass.  MODE: 0 -> g_x32, 1 -> g_wq, 2 -> g_wp
// ---------------------------------------------------------------------------
template <int MODE>
__global__ void __launch_bounds__(256)
round_tf32(const float* __restrict__ src, int n4)
{
    float* dst = (MODE == 0) ? g_x32 : (MODE == 1) ? g_wq : g_wp;
    int i = blockIdx.x * 256 + threadIdx.x;
    if (i < n4) {
        float4 v = reinterpret_cast<const float4*>(src)[i];
        v.x = rna_tf32(v.x); v.y = rna_tf32(v.y);
        v.z = rna_tf32(v.z); v.w = rna_tf32(v.w);
        reinterpret_cast<float4*>(dst)[i] = v;
    }
}

// ---------------------------------------------------------------------------
// tf32 mma.sync NT GEMM (verified in round 4) — unchanged.
// ---------------------------------------------------------------------------
#define ASTRIDE   36
#define ABLK_F    (128 * ASTRIDE)
#define STAGE_F   (2 * ABLK_F)
#define GEMM_SMEM (2 * STAGE_F * 4)

template <int MODE>
__global__ void __launch_bounds__(256)
gemm_mma(const float* __restrict__ bias, float* __restrict__ Cout, int M)
{
    extern __shared__ float sm[];
    const uint32_t sbase = smem_u32(sm);

    const float* __restrict__ A  = (MODE == 0) ? g_x32 : g_ao;
    const float* __restrict__ Bm = (MODE == 0) ? g_wq  : g_wp;

    const int tid    = threadIdx.x;
    const int blockM = blockIdx.y * 128;
    const int blockN = blockIdx.x * 128;

    const int lrow  = tid >> 1;
    const int lhalf = tid & 1;
    const int arow  = blockM + lrow;
    const bool aok  = arow < M;
    const float* aptr = A  + (size_t)(aok ? arow : 0) * KDIM + lhalf * 16;
    const float* bptr = Bm + (size_t)(blockN + lrow) * KDIM + lhalf * 16;
    const uint32_t adst = sbase + (uint32_t)(lrow * ASTRIDE + lhalf * 16) * 4;
    const uint32_t bdst = adst + ABLK_F * 4;
    const int asz = aok ? 16 : 0;

#define LOADC(c) do {                                                          \
        uint32_t _so = ((c) & 1) * (STAGE_F * 4);                              \
        const float* _as = aptr + (c) * 32;                                    \
        const float* _bs = bptr + (c) * 32;                                    \
        _Pragma("unroll")                                                      \
        for (int _i = 0; _i < 4; ++_i)                                         \
            asm volatile("cp.async.cg.shared.global [%0], [%1], 16, %2;"       \
                :: "r"(adst + _so + _i * 16), "l"(_as + _i * 4), "r"(asz));    \
        _Pragma("unroll")                                                      \
        for (int _i = 0; _i < 4; ++_i)                                         \
            asm volatile("cp.async.cg.shared.global [%0], [%1], 16, 16;"       \
                :: "r"(bdst + _so + _i * 16), "l"(_bs + _i * 4));              \
        asm volatile("cp.async.commit_group;");                                \
    } while (0)

    const int lane  = tid & 31;
    const int wid   = tid >> 5;
    const int warpM = (wid & 3) * 32;
    const int warpN = (wid >> 2) * 64;
    const int tq    = lane >> 2;
    const int tr    = lane & 3;

    float acc[2][8][4];
#pragma unroll
    for (int mt = 0; mt < 2; ++mt)
#pragma unroll
        for (int nt = 0; nt < 8; ++nt)
#pragma unroll
            for (int e = 0; e < 4; ++e) acc[mt][nt][e] = 0.f;

    LOADC(0);

    for (int c = 0; c < NCHUNK; ++c) {
        if (c + 1 < NCHUNK) {
            LOADC(c + 1);
            asm volatile("cp.async.wait_group 1;");
        } else {
            asm volatile("cp.async.wait_group 0;");
        }
        __syncthreads();

        const float* As = sm + (c & 1) * STAGE_F;
        const float* Bs = As + ABLK_F;

#pragma unroll
        for (int ks = 0; ks < 4; ++ks) {
            const int k0 = ks * 8;
            uint32_t af[2][4];
#pragma unroll
            for (int mt = 0; mt < 2; ++mt) {
                const float* ap = As + (warpM + mt * 16 + tq) * ASTRIDE + k0 + tr;
                af[mt][0] = __float_as_uint(ap[0]);
                af[mt][1] = __float_as_uint(ap[8 * ASTRIDE]);
                af[mt][2] = __float_as_uint(ap[4]);
                af[mt][3] = __float_as_uint(ap[8 * ASTRIDE + 4]);
            }
#pragma unroll
            for (int nt = 0; nt < 8; ++nt) {
                const float* bp = Bs + (warpN + nt * 8 + tq) * ASTRIDE + k0 + tr;
                uint32_t bf[2] = { __float_as_uint(bp[0]), __float_as_uint(bp[4]) };
#pragma unroll
                for (int mt = 0; mt < 2; ++mt)
                    mma_tf32(acc[mt][nt], af[mt], bf);
            }
        }
        __syncthreads();
    }
#undef LOADC

#pragma unroll
    for (int mt = 0; mt < 2; ++mt) {
#pragma unroll
        for (int half = 0; half < 2; ++half) {
            const int row = blockM + warpM + mt * 16 + tq + half * 8;
            if (row >= M) continue;
            int b = 0, n = 0;
            if (MODE == 0) { b = row / NN; n = row - b * NN; }
#pragma unroll
            for (int nt = 0; nt < 8; ++nt) {
                const int col = blockN + warpN + nt * 8 + tr * 2;
                const float vx = acc[mt][nt][half * 2 + 0];
                const float vy = acc[mt][nt][half * 2 + 1];
                if (MODE == 0) {
                    const int s   = col / CC;
                    const int rem = col - s * CC;
                    const int h   = rem >> 6;
                    const int d   = rem & 63;
                    const float scl = (s == 0) ? 0.125f : 1.f;
                    float* dp = (s == 0 ? g_q : (s == 1 ? g_k : g_v)) +
                                (((size_t)b * HH + h) * NN + n) * HD + d;
                    *reinterpret_cast<float2*>(dp) = make_float2(vx * scl, vy * scl);
                } else {
                    *reinterpret_cast<float2*>(Cout + (size_t)row * CC + col) =
                        make_float2(vx + bias[col], vy + bias[col + 1]);
                }
            }
        }
    }
}

// ---------------------------------------------------------------------------
// Bias precompute (rows 0..784 only; pad rows stay zero-init)
// ---------------------------------------------------------------------------
__global__ void __launch_bounds__(256)
bias_kernel(const float* __restrict__ rel_table,
            const float* __restrict__ g2l,
            const float* __restrict__ g2g)
{
    const int h = blockIdx.x;
    const int i = blockIdx.y;
    float* row = g_bias + ((size_t)h * BROWS + i) * BSTR;
    const int xi = (i - 1) / WXY, yi = (i - 1) % WXY;
    for (int j = threadIdx.x; j < NN; j += 256) {
        float v;
        if (i == 0)      v = (j == 0) ? g2g[h] : g2l[h];
        else if (j == 0) v = g2l[HH + h];
        else {
            int xj = (j - 1) / WXY, yj = (j - 1) % WXY;
            int idx = (xi - xj + (WXY - 1)) * RELW + (yi - yj + (WXY - 1));
            v = rel_table[idx * HH + h];
        }
        row[j] = v;
    }
}

// ---------------------------------------------------------------------------
// Flash attention on mma.sync tf32.
// Block = 128 queries x one (b,h); 8 warps, warp owns 16 full query rows.
// Key tiles of 64, double-buffered cp.async K/V.
// Smem: QP[128*68] (Q staging, then P), K[2][64*68], V[2][64*72].
// ---------------------------------------------------------------------------
#define QP_F   (128 * 68)                  // 8704
#define KS_F   (64 * 68)                   // 4352
#define VS_F   (64 * 72)                   // 4608
#define ATTN_SMEM ((QP_F + 2 * (KS_F + VS_F)) * 4)   // 106496 B

__global__ void __launch_bounds__(256)
attn_mma()
{
    extern __shared__ float sm[];
    float* QP = sm;                        // Q staging, then P (per-warp rows)
    const uint32_t sbase = smem_u32(sm);

    const int bh = blockIdx.y;
    const int b  = bh / HH;
    const int h  = bh - b * HH;
    const int q0 = blockIdx.x * 128;

    const int tid  = threadIdx.x;
    const int lane = tid & 31;
    const int wid  = tid >> 5;
    const int tq   = lane >> 2;
    const int tr   = lane & 3;
    const int r0   = wid * 16;            // warp's query-row base within tile

    const float* Qg = g_q + (size_t)bh * NN * HD;
    const float* Kg = g_k + (size_t)bh * NN * HD;
    const float* Vg = g_v + (size_t)bh * NN * HD;
    const float* Bh = g_bias + (size_t)h * BROWS * BSTR;

    // ---- stage Q tile [128][64] into QP (stride 68) ----
#pragma unroll
    for (int u = 0; u < 8; ++u) {
        const int lin = tid + u * 256;
        const int row = lin >> 4;
        const int c4  = (lin & 15) * 4;
        const int gi  = q0 + row;
        float4 v = make_float4(0.f, 0.f, 0.f, 0.f);
        if (gi < NN) v = *reinterpret_cast<const float4*>(Qg + (size_t)gi * HD + c4);
        *reinterpret_cast<float4*>(QP + row * 68 + c4) = v;
    }
    __syncthreads();

    // ---- Q A-fragments to registers (loop-invariant) ----
    uint32_t qf[8][4];
#pragma unroll
    for (int ks = 0; ks < 8; ++ks) {
        const float* ap = QP + (r0 + tq) * 68 + ks * 8 + tr;
        qf[ks][0] = __float_as_uint(ap[0]);
        qf[ks][1] = __float_as_uint(ap[8 * 68]);
        qf[ks][2] = __float_as_uint(ap[4]);
        qf[ks][3] = __float_as_uint(ap[8 * 68 + 4]);
    }
    __syncthreads();    // QP now free -> P buffer

    // ---- K/V cp.async mapping (per stage: 4 x 16B each) ----
    const int lrow = tid >> 4;            // 0..15 -> covers 64 rows over u=0..3
    const int lc4  = (tid & 15) * 4;

#define KV_LOAD(kt) do {                                                        \
        const int _k0 = (kt) * 64;                                              \
        const uint32_t _ks = sbase + (QP_F + ((kt) & 1) * (KS_F + VS_F)) * 4;   \
        const uint32_t _vs = _ks + KS_F * 4;                                    \
        _Pragma("unroll")                                                       \
        for (int _u = 0; _u < 4; ++_u) {                                        \
            const int _r = lrow + _u * 16;                                      \
            const int _j = _k0 + _r;                                            \
            const int _sz = (_j < NN) ? 16 : 0;                                 \
            asm volatile("cp.async.cg.shared.global [%0], [%1], 16, %2;"        \
                :: "r"(_ks + (_r * 68 + lc4) * 4),                              \
                   "l"(Kg + (size_t)_j * HD + lc4), "r"(_sz));                  \
            asm volatile("cp.async.cg.shared.global [%0], [%1], 16, %2;"        \
                :: "r"(_vs + (_r * 72 + lc4) * 4),                              \
                   "l"(Vg + (size_t)_j * HD + lc4), "r"(_sz));                  \
        }                                                                       \
        asm volatile("cp.async.commit_group;");                                 \
    } while (0)

    float oacc[8][4];
#pragma unroll
    for (int nt = 0; nt < 8; ++nt)
#pragma unroll
        for (int e = 0; e < 4; ++e) oacc[nt][e] = 0.f;
    float mrow[2] = {-1e30f, -1e30f};
    float lrow_s[2] = {0.f, 0.f};

    KV_LOAD(0);

    for (int kt = 0; kt < 13; ++kt) {
        const int k0 = kt * 64;
        if (kt + 1 < 13) {
            KV_LOAD(kt + 1);
            asm volatile("cp.async.wait_group 1;");
        } else {
            asm volatile("cp.async.wait_group 0;");
        }
        __syncthreads();

        const float* Ks = sm + QP_F + (kt & 1) * (KS_F + VS_F);
        const float* Vs = Ks + KS_F;

        // ---- S = Q K^T ----
        float sacc[8][4];
#pragma unroll
        for (int nt = 0; nt < 8; ++nt)
#pragma unroll
            for (int e = 0; e < 4; ++e) sacc[nt][e] = 0.f;

#pragma unroll
        for (int ks = 0; ks < 8; ++ks) {
#pragma unroll
            for (int nt = 0; nt < 8; ++nt) {
                const float* bp = Ks + (nt * 8 + tq) * 68 + ks * 8 + tr;
                uint32_t bf[2] = { __float_as_uint(bp[0]), __float_as_uint(bp[4]) };
                mma_tf32(sacc[nt], qf[ks], bf);
            }
        }

        // ---- bias add ----
#pragma unroll
        for (int nt = 0; nt < 8; ++nt) {
#pragma unroll
            for (int hh = 0; hh < 2; ++hh) {
                const int row = q0 + r0 + tq + 8 * hh;
                const int col = k0 + nt * 8 + 2 * tr;
                const float2 bb = __ldg(reinterpret_cast<const float2*>(
                    Bh + (size_t)row * BSTR + col));
                sacc[nt][2 * hh + 0] += bb.x;
                sacc[nt][2 * hh + 1] += bb.y;
            }
        }
        // ---- mask invalid keys (last tile) ----
        if (k0 + 64 > NN) {
#pragma unroll
            for (int nt = 0; nt < 8; ++nt)
#pragma unroll
                for (int e = 0; e < 4; ++e) {
                    const int col = k0 + nt * 8 + 2 * tr + (e & 1);
                    if (col >= NN) sacc[nt][e] = -1e30f;
                }
        }

        // ---- online softmax (rows tq and tq+8; quad-local reductions) ----
#pragma unroll
        for (int hh = 0; hh < 2; ++hh) {
            float mx = -1e30f;
#pragma unroll
            for (int nt = 0; nt < 8; ++nt)
                mx = fmaxf(mx, fmaxf(sacc[nt][2 * hh], sacc[nt][2 * hh + 1]));
            mx = fmaxf(mx, __shfl_xor_sync(0xffffffffu, mx, 1));
            mx = fmaxf(mx, __shfl_xor_sync(0xffffffffu, mx, 2));
            const float mnew = fmaxf(mrow[hh], mx);
            const float corr = __expf(mrow[hh] - mnew);
            mrow[hh] = mnew;
            float ps = 0.f;
#pragma unroll
            for (int nt = 0; nt < 8; ++nt) {
                const float e0 = __expf(sacc[nt][2 * hh] - mnew);
                const float e1 = __expf(sacc[nt][2 * hh + 1] - mnew);
                sacc[nt][2 * hh] = e0; sacc[nt][2 * hh + 1] = e1;
                ps += e0 + e1;
            }
            ps += __shfl_xor_sync(0xffffffffu, ps, 1);
            ps += __shfl_xor_sync(0xffffffffu, ps, 2);
            lrow_s[hh] = lrow_s[hh] * corr + ps;
#pragma unroll
            for (int nt = 0; nt < 8; ++nt) {
                oacc[nt][2 * hh] *= corr;
                oacc[nt][2 * hh + 1] *= corr;
            }
        }

        // ---- stage P to smem (per-warp rows; warp-local hazard only) ----
#pragma unroll
        for (int nt = 0; nt < 8; ++nt) {
            *reinterpret_cast<float2*>(QP + (r0 + tq) * 68 + nt * 8 + 2 * tr) =
                make_float2(sacc[nt][0], sacc[nt][1]);
            *reinterpret_cast<float2*>(QP + (r0 + tq + 8) * 68 + nt * 8 + 2 * tr) =
                make_float2(sacc[nt][2], sacc[nt][3]);
        }
        __syncwarp();

        // ---- O += P V ----
#pragma unroll
        for (int ks = 0; ks < 8; ++ks) {
            const float* ap = QP + (r0 + tq) * 68 + ks * 8 + tr;
            uint32_t af[4];
            af[0] = __float_as_uint(ap[0]);
            af[1] = __float_as_uint(ap[8 * 68]);
            af[2] = __float_as_uint(ap[4]);
            af[3] = __float_as_uint(ap[8 * 68 + 4]);
#pragma unroll
            for (int nt = 0; nt < 8; ++nt) {
                const float* bp = Vs + (ks * 8 + tr) * 72 + nt * 8 + tq;
                uint32_t bf[2] = { __float_as_uint(bp[0]),
                                   __float_as_uint(bp[4 * 72]) };
                mma_tf32(oacc[nt], af, bf);
            }
        }
        __syncthreads();   // done with this K/V stage + P before reuse
    }
#undef KV_LOAD

    // ---- normalize + write g_ao (tf32-rounded) ----
#pragma unroll
    for (int hh = 0; hh < 2; ++hh) {
        const int i = q0 + r0 + tq + 8 * hh;
        if (i < NN) {
            const float inv = 1.f / lrow_s[hh];
#pragma unroll
            for (int nt = 0; nt < 8; ++nt) {
                float2 w = make_float2(oacc[nt][2 * hh] * inv,
                                       oacc[nt][2 * hh + 1] * inv);
                w.x = rna_tf32(w.x); w.y = rna_tf32(w.y);
                *reinterpret_cast<float2*>(
                    g_ao + ((size_t)b * NN + i) * CC + h * HD + nt * 8 + 2 * tr) = w;
            }
        }
    }
}

// ---------------------------------------------------------------------------
extern "C" void kernel_launch(void* const* d_in, const int* in_sizes, int n_in,
                              void* d_out, int out_size)
{
    const float* x         = (const float*)d_in[0];
    const float* qkv_w     = (const float*)d_in[1];
    const float* proj_w    = (const float*)d_in[2];
    const float* proj_b    = (const float*)d_in[3];
    const float* rel_table = (const float*)d_in[4];
    const float* g2l       = (const float*)d_in[5];
    const float* g2g       = (const float*)d_in[6];
    float* out = (float*)d_out;

    (void)in_sizes; (void)n_in; (void)out_size;

    cudaFuncSetAttribute(attn_mma,
                         cudaFuncAttributeMaxDynamicSharedMemorySize, ATTN_SMEM);
    cudaFuncSetAttribute(gemm_mma<0>,
                         cudaFuncAttributeMaxDynamicSharedMemorySize, GEMM_SMEM);
    cudaFuncSetAttribute(gemm_mma<1>,
                         cudaFuncAttributeMaxDynamicSharedMemorySize, GEMM_SMEM);

    // 0) tf32 rounding pre-passes + bias precompute
    {
        int n4x = MROWS * CC / 4, n4q = QKVN * CC / 4, n4p = CC * CC / 4;
        round_tf32<0><<<(n4x + 255) / 256, 256>>>(x, n4x);
        round_tf32<1><<<(n4q + 255) / 256, 256>>>(qkv_w, n4q);
        round_tf32<2><<<(n4p + 255) / 256, 256>>>(proj_w, n4p);
        dim3 gb(HH, NN);
        bias_kernel<<<gb, 256>>>(rel_table, g2l, g2g);
    }
    // 1) QKV GEMM (tf32 mma.sync)
    {
        dim3 grid(QKVN / 128, (MROWS + 127) / 128);   // (18, 99)
        gemm_mma<0><<<grid, 256, GEMM_SMEM>>>(nullptr, nullptr, MROWS);
    }
    // 2) flash attention (tf32 mma.sync) -> g_ao
    {
        dim3 grid((NN + 127) / 128, BB * HH);         // (7, 192)
        attn_mma<<<grid, 256, ATTN_SMEM>>>();
    }
    // 3) proj GEMM (tf32 mma.sync) + bias -> out
    {
        dim3 grid(CC / 128, (MROWS + 127) / 128);     // (6, 99)
        gemm_mma<1><<<grid, 256, GEMM_SMEM>>>(proj_b, out, MROWS);
    }
}

// round 7
// speedup vs baseline: 8.7667x; 1.0083x over previous
#include <cuda_runtime.h>
#include <cuda_bf16.h>
#include <cstdint>

// Problem constants
#define BB    16
#define NN    785
#define CC    768
#define HH    12
#define HD    64
#define MROWS (BB * NN)      // 12560
#define QKVN  (3 * CC)       // 2304
#define WXY   28
#define RELW  55
#define BROWS 896            // padded query rows for bias (7 * 128)
#define BSTR  836
#define KDIM  768
#define NCHUNK 24            // 768 / 32

// -------- scratch (static device arrays; no allocations allowed) ----------
__device__ float g_x32[MROWS * CC];          // x rounded to tf32
__device__ float g_wq [QKVN * CC];           // qkv_w rounded to tf32
__device__ float g_wp [CC * CC];             // proj_w rounded to tf32
__device__ float g_q  [BB * HH * NN * HD];   // [B,H,N,64], Q pre-scaled 1/8
__device__ float g_k  [BB * HH * NN * HD];
__device__ float g_v  [BB * HH * NN * HD];
__device__ float g_ao [MROWS * CC];          // attention out (tf32-rounded)
__device__ float g_bias[HH * BROWS * BSTR];  // [h][i][j] bias (pad rows stay 0)

// ---------------------------------------------------------------------------
__device__ __forceinline__ uint32_t smem_u32(const void* p) {
    uint32_t a;
    asm("{ .reg .u64 t; cvta.to.shared.u64 t, %1; cvt.u32.u64 %0, t; }"
        : "=r"(a) : "l"(p));
    return a;
}
__device__ __forceinline__ float rna_tf32(float v) {
    uint32_t u;
    asm("cvt.rna.tf32.f32 %0, %1;" : "=r"(u) : "f"(v));
    return __uint_as_float(u);
}
__device__ __forceinline__ void mma_tf32(float* d, const uint32_t* a,
                                         const uint32_t* b) {
    asm volatile(
        "mma.sync.aligned.m16n8k8.row.col.f32.tf32.tf32.f32 "
        "{%0,%1,%2,%3}, {%4,%5,%6,%7}, {%8,%9}, {%0,%1,%2,%3};"
        : "+f"(d[0]), "+f"(d[1]), "+f"(d[2]), "+f"(d[3])
        : "r"(a[0]), "r"(a[1]), "r"(a[2]), "r"(a[3]), "r"(b[0]), "r"(b[1]));
}

// ---------------------------------------------------------------------------
// tf32 rounding pre-pass, all three tensors in one launch.
// ---------------------------------------------------------------------------
#define N4X (MROWS * CC / 4)
#define N4Q (QKVN * CC / 4)
#define N4P (CC * CC / 4)

__global__ void __launch_bounds__(256)
round_all(const float* __restrict__ x, const float* __restrict__ wq,
          const float* __restrict__ wp)
{
    int i = blockIdx.x * 256 + threadIdx.x;
    const float* src;
    float* dst;
    if (i < N4X)                  { src = x;  dst = g_x32; }
    else if (i < N4X + N4Q)       { src = wq; dst = g_wq;  i -= N4X; }
    else if (i < N4X + N4Q + N4P) { src = wp; dst = g_wp;  i -= N4X + N4Q; }
    else return;
    float4 v = reinterpret_cast<const float4*>(src)[i];
    v.x = rna_tf32(v.x); v.y = rna_tf32(v.y);
    v.z = rna_tf32(v.z); v.w = rna_tf32(v.w);
    reinterpret_cast<float4*>(dst)[i] = v;
}

// ---------------------------------------------------------------------------
// tf32 mma.sync NT GEMM — round-4 body, pinned to 2 CTAs/SM.
// ---------------------------------------------------------------------------
#define ASTRIDE   36
#define ABLK_F    (128 * ASTRIDE)
#define STAGE_F   (2 * ABLK_F)
#define GEMM_SMEM (2 * STAGE_F * 4)      // 73728 B -> 2 CTAs/SM

template <int MODE>
__global__ void __launch_bounds__(256, 2)
gemm_mma(const float* __restrict__ bias, float* __restrict__ Cout, int M)
{
    extern __shared__ float sm[];
    const uint32_t sbase = smem_u32(sm);

    const float* __restrict__ A  = (MODE == 0) ? g_x32 : g_ao;
    const float* __restrict__ Bm = (MODE == 0) ? g_wq  : g_wp;

    const int tid    = threadIdx.x;
    const int blockM = blockIdx.y * 128;
    const int blockN = blockIdx.x * 128;

    const int lrow  = tid >> 1;
    const int lhalf = tid & 1;
    const int arow  = blockM + lrow;
    const bool aok  = arow < M;
    const float* aptr = A  + (size_t)(aok ? arow : 0) * KDIM + lhalf * 16;
    const float* bptr = Bm + (size_t)(blockN + lrow) * KDIM + lhalf * 16;
    const uint32_t adst = sbase + (uint32_t)(lrow * ASTRIDE + lhalf * 16) * 4;
    const uint32_t bdst = adst + ABLK_F * 4;
    const int asz = aok ? 16 : 0;

#define LOADC(c) do {                                                          \
        uint32_t _so = ((c) & 1) * (STAGE_F * 4);                              \
        const float* _as = aptr + (c) * 32;                                    \
        const float* _bs = bptr + (c) * 32;                                    \
        _Pragma("unroll")                                                      \
        for (int _i = 0; _i < 4; ++_i)                                         \
            asm volatile("cp.async.cg.shared.global [%0], [%1], 16, %2;"       \
                :: "r"(adst + _so + _i * 16), "l"(_as + _i * 4), "r"(asz));    \
        _Pragma("unroll")                                                      \
        for (int _i = 0; _i < 4; ++_i)                                         \
            asm volatile("cp.async.cg.shared.global [%0], [%1], 16, 16;"       \
                :: "r"(bdst + _so + _i * 16), "l"(_bs + _i * 4));              \
        asm volatile("cp.async.commit_group;");                                \
    } while (0)

    const int lane  = tid & 31;
    const int wid   = tid >> 5;
    const int warpM = (wid & 3) * 32;
    const int warpN = (wid >> 2) * 64;
    const int tq    = lane >> 2;
    const int tr    = lane & 3;

    float acc[2][8][4];
#pragma unroll
    for (int mt = 0; mt < 2; ++mt)
#pragma unroll
        for (int nt = 0; nt < 8; ++nt)
#pragma unroll
            for (int e = 0; e < 4; ++e) acc[mt][nt][e] = 0.f;

    LOADC(0);

    for (int c = 0; c < NCHUNK; ++c) {
        if (c + 1 < NCHUNK) {
            LOADC(c + 1);
            asm volatile("cp.async.wait_group 1;");
        } else {
            asm volatile("cp.async.wait_group 0;");
        }
        __syncthreads();

        const float* As = sm + (c & 1) * STAGE_F;
        const float* Bs = As + ABLK_F;

#pragma unroll
        for (int ks = 0; ks < 4; ++ks) {
            const int k0 = ks * 8;
            uint32_t af[2][4];
#pragma unroll
            for (int mt = 0; mt < 2; ++mt) {
                const float* ap = As + (warpM + mt * 16 + tq) * ASTRIDE + k0 + tr;
                af[mt][0] = __float_as_uint(ap[0]);
                af[mt][1] = __float_as_uint(ap[8 * ASTRIDE]);
                af[mt][2] = __float_as_uint(ap[4]);
                af[mt][3] = __float_as_uint(ap[8 * ASTRIDE + 4]);
            }
#pragma unroll
            for (int nt = 0; nt < 8; ++nt) {
                const float* bp = Bs + (warpN + nt * 8 + tq) * ASTRIDE + k0 + tr;
                uint32_t bf[2] = { __float_as_uint(bp[0]), __float_as_uint(bp[4]) };
#pragma unroll
                for (int mt = 0; mt < 2; ++mt)
                    mma_tf32(acc[mt][nt], af[mt], bf);
            }
        }
        __syncthreads();
    }
#undef LOADC

#pragma unroll
    for (int mt = 0; mt < 2; ++mt) {
#pragma unroll
        for (int half = 0; half < 2; ++half) {
            const int row = blockM + warpM + mt * 16 + tq + half * 8;
            if (row >= M) continue;
            int b = 0, n = 0;
            if (MODE == 0) { b = row / NN; n = row - b * NN; }
#pragma unroll
            for (int nt = 0; nt < 8; ++nt) {
                const int col = blockN + warpN + nt * 8 + tr * 2;
                const float vx = acc[mt][nt][half * 2 + 0];
                const float vy = acc[mt][nt][half * 2 + 1];
                if (MODE == 0) {
                    const int s   = col / CC;
                    const int rem = col - s * CC;
                    const int h   = rem >> 6;
                    const int d   = rem & 63;
                    const float scl = (s == 0) ? 0.125f : 1.f;
                    float* dp = (s == 0 ? g_q : (s == 1 ? g_k : g_v)) +
                                (((size_t)b * HH + h) * NN + n) * HD + d;
                    *reinterpret_cast<float2*>(dp) = make_float2(vx * scl, vy * scl);
                } else {
                    *reinterpret_cast<float2*>(Cout + (size_t)row * CC + col) =
                        make_float2(vx + bias[col], vy + bias[col + 1]);
                }
            }
        }
    }
}

// ---------------------------------------------------------------------------
// Bias precompute (rows 0..784 only; pad rows stay zero-init)
// ---------------------------------------------------------------------------
__global__ void __launch_bounds__(256)
bias_kernel(const float* __restrict__ rel_table,
            const float* __restrict__ g2l,
            const float* __restrict__ g2g)
{
    const int h = blockIdx.x;
    const int i = blockIdx.y;
    float* row = g_bias + ((size_t)h * BROWS + i) * BSTR;
    const int xi = (i - 1) / WXY, yi = (i - 1) % WXY;
    for (int j = threadIdx.x; j < NN; j += 256) {
        float v;
        if (i == 0)      v = (j == 0) ? g2g[h] : g2l[h];
        else if (j == 0) v = g2l[HH + h];
        else {
            int xj = (j - 1) / WXY, yj = (j - 1) % WXY;
            int idx = (xi - xj + (WXY - 1)) * RELW + (yi - yj + (WXY - 1));
            v = rel_table[idx * HH + h];
        }
        row[j] = v;
    }
}

// ---------------------------------------------------------------------------
// Flash attention on mma.sync tf32 (verified round-5 version, unchanged).
// ---------------------------------------------------------------------------
#define QP_F   (128 * 68)
#define KS_F   (64 * 68)
#define VS_F   (64 * 72)
#define ATTN_SMEM ((QP_F + 2 * (KS_F + VS_F)) * 4)   // 106496 B

__global__ void __launch_bounds__(256)
attn_mma()
{
    extern __shared__ float sm[];
    float* QP = sm;
    const uint32_t sbase = smem_u32(sm);

    const int bh = blockIdx.y;
    const int b  = bh / HH;
    const int h  = bh - b * HH;
    const int q0 = blockIdx.x * 128;

    const int tid  = threadIdx.x;
    const int lane = tid & 31;
    const int wid  = tid >> 5;
    const int tq   = lane >> 2;
    const int tr   = lane & 3;
    const int r0   = wid * 16;

    const float* Qg = g_q + (size_t)bh * NN * HD;
    const float* Kg = g_k + (size_t)bh * NN * HD;
    const float* Vg = g_v + (size_t)bh * NN * HD;
    const float* Bh = g_bias + (size_t)h * BROWS * BSTR;

#pragma unroll
    for (int u = 0; u < 8; ++u) {
        const int lin = tid + u * 256;
        const int row = lin >> 4;
        const int c4  = (lin & 15) * 4;
        const int gi  = q0 + row;
        float4 v = make_float4(0.f, 0.f, 0.f, 0.f);
        if (gi < NN) v = *reinterpret_cast<const float4*>(Qg + (size_t)gi * HD + c4);
        *reinterpret_cast<float4*>(QP + row * 68 + c4) = v;
    }
    __syncthreads();

    uint32_t qf[8][4];
#pragma unroll
    for (int ks = 0; ks < 8; ++ks) {
        const float* ap = QP + (r0 + tq) * 68 + ks * 8 + tr;
        qf[ks][0] = __float_as_uint(ap[0]);
        qf[ks][1] = __float_as_uint(ap[8 * 68]);
        qf[ks][2] = __float_as_uint(ap[4]);
        qf[ks][3] = __float_as_uint(ap[8 * 68 + 4]);
    }
    __syncthreads();

    const int lrow = tid >> 4;
    const int lc4  = (tid & 15) * 4;

#define KV_LOAD(kt) do {                                                        \
        const int _k0 = (kt) * 64;                                              \
        const uint32_t _ks = sbase + (QP_F + ((kt) & 1) * (KS_F + VS_F)) * 4;   \
        const uint32_t _vs = _ks + KS_F * 4;                                    \
        _Pragma("unroll")                                                       \
        for (int _u = 0; _u < 4; ++_u) {                                        \
            const int _r = lrow + _u * 16;                                      \
            const int _j = _k0 + _r;                                            \
            const int _sz = (_j < NN) ? 16 : 0;                                 \
            asm volatile("cp.async.cg.shared.global [%0], [%1], 16, %2;"        \
                :: "r"(_ks + (_r * 68 + lc4) * 4),                              \
                   "l"(Kg + (size_t)_j * HD + lc4), "r"(_sz));                  \
            asm volatile("cp.async.cg.shared.global [%0], [%1], 16, %2;"        \
                :: "r"(_vs + (_r * 72 + lc4) * 4),                              \
                   "l"(Vg + (size_t)_j * HD + lc4), "r"(_sz));                  \
        }                                                                       \
        asm volatile("cp.async.commit_group;");                                 \
    } while (0)

    float oacc[8][4];
#pragma unroll
    for (int nt = 0; nt < 8; ++nt)
#pragma unroll
        for (int e = 0; e < 4; ++e) oacc[nt][e] = 0.f;
    float mrow[2] = {-1e30f, -1e30f};
    float lrow_s[2] = {0.f, 0.f};

    KV_LOAD(0);

    for (int kt = 0; kt < 13; ++kt) {
        const int k0 = kt * 64;
        if (kt + 1 < 13) {
            KV_LOAD(kt + 1);
            asm volatile("cp.async.wait_group 1;");
        } else {
            asm volatile("cp.async.wait_group 0;");
        }
        __syncthreads();

        const float* Ks = sm + QP_F + (kt & 1) * (KS_F + VS_F);
        const float* Vs = Ks + KS_F;

        float sacc[8][4];
#pragma unroll
        for (int nt = 0; nt < 8; ++nt)
#pragma unroll
            for (int e = 0; e < 4; ++e) sacc[nt][e] = 0.f;

#pragma unroll
        for (int ks = 0; ks < 8; ++ks) {
#pragma unroll
            for (int nt = 0; nt < 8; ++nt) {
                const float* bp = Ks + (nt * 8 + tq) * 68 + ks * 8 + tr;
                uint32_t bf[2] = { __float_as_uint(bp[0]), __float_as_uint(bp[4]) };
                mma_tf32(sacc[nt], qf[ks], bf);
            }
        }

#pragma unroll
        for (int nt = 0; nt < 8; ++nt) {
#pragma unroll
            for (int hh = 0; hh < 2; ++hh) {
                const int row = q0 + r0 + tq + 8 * hh;
                const int col = k0 + nt * 8 + 2 * tr;
                const float2 bb = __ldg(reinterpret_cast<const float2*>(
                    Bh + (size_t)row * BSTR + col));
                sacc[nt][2 * hh + 0] += bb.x;
                sacc[nt][2 * hh + 1] += bb.y;
            }
        }
        if (k0 + 64 > NN) {
#pragma unroll
            for (int nt = 0; nt < 8; ++nt)
#pragma unroll
                for (int e = 0; e < 4; ++e) {
                    const int col = k0 + nt * 8 + 2 * tr + (e & 1);
                    if (col >= NN) sacc[nt][e] = -1e30f;
                }
        }

#pragma unroll
        for (int hh = 0; hh < 2; ++hh) {
            float mx = -1e30f;
#pragma unroll
            for (int nt = 0; nt < 8; ++nt)
                mx = fmaxf(mx, fmaxf(sacc[nt][2 * hh], sacc[nt][2 * hh + 1]));
            mx = fmaxf(mx, __shfl_xor_sync(0xffffffffu, mx, 1));
            mx = fmaxf(mx, __shfl_xor_sync(0xffffffffu, mx, 2));
            const float mnew = fmaxf(mrow[hh], mx);
            const float corr = __expf(mrow[hh] - mnew);
            mrow[hh] = mnew;
            float ps = 0.f;
#pragma unroll
            for (int nt = 0; nt < 8; ++nt) {
                const float e0 = __expf(sacc[nt][2 * hh] - mnew);
                const float e1 = __expf(sacc[nt][2 * hh + 1] - mnew);
                sacc[nt][2 * hh] = e0; sacc[nt][2 * hh + 1] = e1;
                ps += e0 + e1;
            }
            ps += __shfl_xor_sync(0xffffffffu, ps, 1);
            ps += __shfl_xor_sync(0xffffffffu, ps, 2);
            lrow_s[hh] = lrow_s[hh] * corr + ps;
#pragma unroll
            for (int nt = 0; nt < 8; ++nt) {
                oacc[nt][2 * hh] *= corr;
                oacc[nt][2 * hh + 1] *= corr;
            }
        }

#pragma unroll
        for (int nt = 0; nt < 8; ++nt) {
            *reinterpret_cast<float2*>(QP + (r0 + tq) * 68 + nt * 8 + 2 * tr) =
                make_float2(sacc[nt][0], sacc[nt][1]);
            *reinterpret_cast<float2*>(QP + (r0 + tq + 8) * 68 + nt * 8 + 2 * tr) =
                make_float2(sacc[nt][2], sacc[nt][3]);
        }
        __syncwarp();

#pragma unroll
        for (int ks = 0; ks < 8; ++ks) {
            const float* ap = QP + (r0 + tq) * 68 + ks * 8 + tr;
            uint32_t af[4];
            af[0] = __float_as_uint(ap[0]);
            af[1] = __float_as_uint(ap[8 * 68]);
            af[2] = __float_as_uint(ap[4]);
            af[3] = __float_as_uint(ap[8 * 68 + 4]);
#pragma unroll
            for (int nt = 0; nt < 8; ++nt) {
                const float* bp = Vs + (ks * 8 + tr) * 72 + nt * 8 + tq;
                uint32_t bf[2] = { __float_as_uint(bp[0]),
                                   __float_as_uint(bp[4 * 72]) };
                mma_tf32(oacc[nt], af, bf);
            }
        }
        __syncthreads();
    }
#undef KV_LOAD

#pragma unroll
    for (int hh = 0; hh < 2; ++hh) {
        const int i = q0 + r0 + tq + 8 * hh;
        if (i < NN) {
            const float inv = 1.f / lrow_s[hh];
#pragma unroll
            for (int nt = 0; nt < 8; ++nt) {
                float2 w = make_float2(oacc[nt][2 * hh] * inv,
                                       oacc[nt][2 * hh + 1] * inv);
                w.x = rna_tf32(w.x); w.y = rna_tf32(w.y);
                *reinterpret_cast<float2*>(
                    g_ao + ((size_t)b * NN + i) * CC + h * HD + nt * 8 + 2 * tr) = w;
            }
        }
    }
}

// ---------------------------------------------------------------------------
extern "C" void kernel_launch(void* const* d_in, const int* in_sizes, int n_in,
                              void* d_out, int out_size)
{
    const float* x         = (const float*)d_in[0];
    const float* qkv_w     = (const float*)d_in[1];
    const float* proj_w    = (const float*)d_in[2];
    const float* proj_b    = (const float*)d_in[3];
    const float* rel_table = (const float*)d_in[4];
    const float* g2l       = (const float*)d_in[5];
    const float* g2g       = (const float*)d_in[6];
    float* out = (float*)d_out;

    (void)in_sizes; (void)n_in; (void)out_size;

    cudaFuncSetAttribute(attn_mma,
                         cudaFuncAttributeMaxDynamicSharedMemorySize, ATTN_SMEM);
    cudaFuncSetAttribute(gemm_mma<0>,
                         cudaFuncAttributeMaxDynamicSharedMemorySize, GEMM_SMEM);
    cudaFuncSetAttribute(gemm_mma<1>,
                         cudaFuncAttributeMaxDynamicSharedMemorySize, GEMM_SMEM);

    // 0) tf32 rounding (single launch) + bias precompute
    {
        int n4 = N4X + N4Q + N4P;
        round_all<<<(n4 + 255) / 256, 256>>>(x, qkv_w, proj_w);
        dim3 gb(HH, NN);
        bias_kernel<<<gb, 256>>>(rel_table, g2l, g2g);
    }
    // 1) QKV GEMM (tf32 mma.sync, 2 CTA/SM)
    {
        dim3 grid(QKVN / 128, (MROWS + 127) / 128);   // (18, 99)
        gemm_mma<0><<<grid, 256, GEMM_SMEM>>>(nullptr, nullptr, MROWS);
    }
    // 2) flash attention (tf32 mma.sync) -> g_ao
    {
        dim3 grid((NN + 127) / 128, BB * HH);         // (7, 192)
        attn_mma<<<grid, 256, ATTN_SMEM>>>();
    }
    // 3) proj GEMM (tf32 mma.sync, 2 CTA/SM) + bias -> out
    {
        dim3 grid(CC / 128, (MROWS + 127) / 128);     // (6, 99)
        gemm_mma<1><<<grid, 256, GEMM_SMEM>>>(proj_b, out, MROWS);
    }
}

// round 8
// speedup vs baseline: 9.1224x; 1.0406x over previous
#include <cuda_runtime.h>
#include <cuda_bf16.h>
#include <cstdint>

// Problem constants
#define BB    16
#define NN    785
#define CC    768
#define HH    12
#define HD    64
#define MROWS (BB * NN)      // 12560
#define QKVN  (3 * CC)       // 2304
#define WXY   28
#define RELW  55
#define BROWS 896            // padded query rows for bias (7 * 128)
#define BSTR  836
#define KDIM  768
#define NCHUNK 24            // 768 / 32

// -------- scratch (static device arrays; no allocations allowed) ----------
__device__ float g_x32[MROWS * CC];          // x rounded to tf32
__device__ float g_wq [QKVN * CC];           // qkv_w rounded to tf32
__device__ float g_wp [CC * CC];             // proj_w rounded to tf32
__device__ float g_q  [BB * HH * NN * HD];   // [B,H,N,64], Q pre-scaled 1/8
__device__ float g_k  [BB * HH * NN * HD];
__device__ float g_v  [BB * HH * NN * HD];
__device__ float g_ao [MROWS * CC];          // attention out (tf32-rounded)
__device__ float g_bias[HH * BROWS * BSTR];  // [h][i][j] bias (pad rows stay 0)

// ---------------------------------------------------------------------------
__device__ __forceinline__ uint32_t smem_u32(const void* p) {
    uint32_t a;
    asm("{ .reg .u64 t; cvta.to.shared.u64 t, %1; cvt.u32.u64 %0, t; }"
        : "=r"(a) : "l"(p));
    return a;
}
__device__ __forceinline__ float rna_tf32(float v) {
    uint32_t u;
    asm("cvt.rna.tf32.f32 %0, %1;" : "=r"(u) : "f"(v));
    return __uint_as_float(u);
}
__device__ __forceinline__ void mma_tf32(float* d, const uint32_t* a,
                                         const uint32_t* b) {
    asm volatile(
        "mma.sync.aligned.m16n8k8.row.col.f32.tf32.tf32.f32 "
        "{%0,%1,%2,%3}, {%4,%5,%6,%7}, {%8,%9}, {%0,%1,%2,%3};"
        : "+f"(d[0]), "+f"(d[1]), "+f"(d[2]), "+f"(d[3])
        : "r"(a[0]), "r"(a[1]), "r"(a[2]), "r"(a[3]), "r"(b[0]), "r"(b[1]));
}

// ---------------------------------------------------------------------------
// tf32 rounding pre-pass, all three tensors in one launch.
// ---------------------------------------------------------------------------
#define N4X (MROWS * CC / 4)
#define N4Q (QKVN * CC / 4)
#define N4P (CC * CC / 4)

__global__ void __launch_bounds__(256)
round_all(const float* __restrict__ x, const float* __restrict__ wq,
          const float* __restrict__ wp)
{
    int i = blockIdx.x * 256 + threadIdx.x;
    const float* src;
    float* dst;
    if (i < N4X)                  { src = x;  dst = g_x32; }
    else if (i < N4X + N4Q)       { src = wq; dst = g_wq;  i -= N4X; }
    else if (i < N4X + N4Q + N4P) { src = wp; dst = g_wp;  i -= N4X + N4Q; }
    else return;
    float4 v = reinterpret_cast<const float4*>(src)[i];
    v.x = rna_tf32(v.x); v.y = rna_tf32(v.y);
    v.z = rna_tf32(v.z); v.w = rna_tf32(v.w);
    reinterpret_cast<float4*>(dst)[i] = v;
}

// ---------------------------------------------------------------------------
// tf32 mma.sync NT GEMM (verified; already 2 CTA/SM) — unchanged.
// ---------------------------------------------------------------------------
#define ASTRIDE   36
#define ABLK_F    (128 * ASTRIDE)
#define STAGE_F   (2 * ABLK_F)
#define GEMM_SMEM (2 * STAGE_F * 4)      // 73728 B

template <int MODE>
__global__ void __launch_bounds__(256, 2)
gemm_mma(const float* __restrict__ bias, float* __restrict__ Cout, int M)
{
    extern __shared__ float sm[];
    const uint32_t sbase = smem_u32(sm);

    const float* __restrict__ A  = (MODE == 0) ? g_x32 : g_ao;
    const float* __restrict__ Bm = (MODE == 0) ? g_wq  : g_wp;

    const int tid    = threadIdx.x;
    const int blockM = blockIdx.y * 128;
    const int blockN = blockIdx.x * 128;

    const int lrow  = tid >> 1;
    const int lhalf = tid & 1;
    const int arow  = blockM + lrow;
    const bool aok  = arow < M;
    const float* aptr = A  + (size_t)(aok ? arow : 0) * KDIM + lhalf * 16;
    const float* bptr = Bm + (size_t)(blockN + lrow) * KDIM + lhalf * 16;
    const uint32_t adst = sbase + (uint32_t)(lrow * ASTRIDE + lhalf * 16) * 4;
    const uint32_t bdst = adst + ABLK_F * 4;
    const int asz = aok ? 16 : 0;

#define LOADC(c) do {                                                          \
        uint32_t _so = ((c) & 1) * (STAGE_F * 4);                              \
        const float* _as = aptr + (c) * 32;                                    \
        const float* _bs = bptr + (c) * 32;                                    \
        _Pragma("unroll")                                                      \
        for (int _i = 0; _i < 4; ++_i)                                         \
            asm volatile("cp.async.cg.shared.global [%0], [%1], 16, %2;"       \
                :: "r"(adst + _so + _i * 16), "l"(_as + _i * 4), "r"(asz));    \
        _Pragma("unroll")                                                      \
        for (int _i = 0; _i < 4; ++_i)                                         \
            asm volatile("cp.async.cg.shared.global [%0], [%1], 16, 16;"       \
                :: "r"(bdst + _so + _i * 16), "l"(_bs + _i * 4));              \
        asm volatile("cp.async.commit_group;");                                \
    } while (0)

    const int lane  = tid & 31;
    const int wid   = tid >> 5;
    const int warpM = (wid & 3) * 32;
    const int warpN = (wid >> 2) * 64;
    const int tq    = lane >> 2;
    const int tr    = lane & 3;

    float acc[2][8][4];
#pragma unroll
    for (int mt = 0; mt < 2; ++mt)
#pragma unroll
        for (int nt = 0; nt < 8; ++nt)
#pragma unroll
            for (int e = 0; e < 4; ++e) acc[mt][nt][e] = 0.f;

    LOADC(0);

    for (int c = 0; c < NCHUNK; ++c) {
        if (c + 1 < NCHUNK) {
            LOADC(c + 1);
            asm volatile("cp.async.wait_group 1;");
        } else {
            asm volatile("cp.async.wait_group 0;");
        }
        __syncthreads();

        const float* As = sm + (c & 1) * STAGE_F;
        const float* Bs = As + ABLK_F;

#pragma unroll
        for (int ks = 0; ks < 4; ++ks) {
            const int k0 = ks * 8;
            uint32_t af[2][4];
#pragma unroll
            for (int mt = 0; mt < 2; ++mt) {
                const float* ap = As + (warpM + mt * 16 + tq) * ASTRIDE + k0 + tr;
                af[mt][0] = __float_as_uint(ap[0]);
                af[mt][1] = __float_as_uint(ap[8 * ASTRIDE]);
                af[mt][2] = __float_as_uint(ap[4]);
                af[mt][3] = __float_as_uint(ap[8 * ASTRIDE + 4]);
            }
#pragma unroll
            for (int nt = 0; nt < 8; ++nt) {
                const float* bp = Bs + (warpN + nt * 8 + tq) * ASTRIDE + k0 + tr;
                uint32_t bf[2] = { __float_as_uint(bp[0]), __float_as_uint(bp[4]) };
#pragma unroll
                for (int mt = 0; mt < 2; ++mt)
                    mma_tf32(acc[mt][nt], af[mt], bf);
            }
        }
        __syncthreads();
    }
#undef LOADC

#pragma unroll
    for (int mt = 0; mt < 2; ++mt) {
#pragma unroll
        for (int half = 0; half < 2; ++half) {
            const int row = blockM + warpM + mt * 16 + tq + half * 8;
            if (row >= M) continue;
            int b = 0, n = 0;
            if (MODE == 0) { b = row / NN; n = row - b * NN; }
#pragma unroll
            for (int nt = 0; nt < 8; ++nt) {
                const int col = blockN + warpN + nt * 8 + tr * 2;
                const float vx = acc[mt][nt][half * 2 + 0];
                const float vy = acc[mt][nt][half * 2 + 1];
                if (MODE == 0) {
                    const int s   = col / CC;
                    const int rem = col - s * CC;
                    const int h   = rem >> 6;
                    const int d   = rem & 63;
                    const float scl = (s == 0) ? 0.125f : 1.f;
                    float* dp = (s == 0 ? g_q : (s == 1 ? g_k : g_v)) +
                                (((size_t)b * HH + h) * NN + n) * HD + d;
                    *reinterpret_cast<float2*>(dp) = make_float2(vx * scl, vy * scl);
                } else {
                    *reinterpret_cast<float2*>(Cout + (size_t)row * CC + col) =
                        make_float2(vx + bias[col], vy + bias[col + 1]);
                }
            }
        }
    }
}

// ---------------------------------------------------------------------------
// Bias precompute (rows 0..784 only; pad rows stay zero-init)
// ---------------------------------------------------------------------------
__global__ void __launch_bounds__(256)
bias_kernel(const float* __restrict__ rel_table,
            const float* __restrict__ g2l,
            const float* __restrict__ g2g)
{
    const int h = blockIdx.x;
    const int i = blockIdx.y;
    float* row = g_bias + ((size_t)h * BROWS + i) * BSTR;
    const int xi = (i - 1) / WXY, yi = (i - 1) % WXY;
    for (int j = threadIdx.x; j < NN; j += 256) {
        float v;
        if (i == 0)      v = (j == 0) ? g2g[h] : g2l[h];
        else if (j == 0) v = g2l[HH + h];
        else {
            int xj = (j - 1) / WXY, yj = (j - 1) % WXY;
            int idx = (xi - xj + (WXY - 1)) * RELW + (yi - yj + (WXY - 1));
            v = rel_table[idx * HH + h];
        }
        row[j] = v;
    }
}

// ---------------------------------------------------------------------------
// Flash attention on mma.sync tf32.  Key tile = 32 (was 64) to cut registers
// (sacc 32->16) and smem (106KB->70.7KB) so 2 CTAs/SM co-reside.
// Block = 128 queries x one (b,h); 8 warps; 25 key tiles, double-buffered.
// ---------------------------------------------------------------------------
#define KT     32
#define NKT    25                         // ceil(785/32)
#define QP_F   (128 * 68)                 // 8704
#define KS_F   (KT * 68)                  // 2176
#define VS_F   (KT * 72)                  // 2304
#define ATTN_SMEM ((QP_F + 2 * (KS_F + VS_F)) * 4)   // 70656 B

__global__ void __launch_bounds__(256, 2)
attn_mma()
{
    extern __shared__ float sm[];
    float* QP = sm;                       // Q staging, then P (per-warp rows)
    const uint32_t sbase = smem_u32(sm);

    const int bh = blockIdx.y;
    const int b  = bh / HH;
    const int h  = bh - b * HH;
    const int q0 = blockIdx.x * 128;

    const int tid  = threadIdx.x;
    const int lane = tid & 31;
    const int wid  = tid >> 5;
    const int tq   = lane >> 2;
    const int tr   = lane & 3;
    const int r0   = wid * 16;

    const float* Qg = g_q + (size_t)bh * NN * HD;
    const float* Kg = g_k + (size_t)bh * NN * HD;
    const float* Vg = g_v + (size_t)bh * NN * HD;
    const float* Bh = g_bias + (size_t)h * BROWS * BSTR;

    // ---- stage Q tile [128][64] into QP (stride 68) ----
#pragma unroll
    for (int u = 0; u < 8; ++u) {
        const int lin = tid + u * 256;
        const int row = lin >> 4;
        const int c4  = (lin & 15) * 4;
        const int gi  = q0 + row;
        float4 v = make_float4(0.f, 0.f, 0.f, 0.f);
        if (gi < NN) v = *reinterpret_cast<const float4*>(Qg + (size_t)gi * HD + c4);
        *reinterpret_cast<float4*>(QP + row * 68 + c4) = v;
    }
    __syncthreads();

    // ---- Q A-fragments to registers (loop-invariant) ----
    uint32_t qf[8][4];
#pragma unroll
    for (int ks = 0; ks < 8; ++ks) {
        const float* ap = QP + (r0 + tq) * 68 + ks * 8 + tr;
        qf[ks][0] = __float_as_uint(ap[0]);
        qf[ks][1] = __float_as_uint(ap[8 * 68]);
        qf[ks][2] = __float_as_uint(ap[4]);
        qf[ks][3] = __float_as_uint(ap[8 * 68 + 4]);
    }
    __syncthreads();    // QP now free -> P buffer

    // ---- K/V cp.async mapping: 32 rows x 64B; 2 x 16B per thread each ----
    const int lrow = tid >> 4;            // 0..15
    const int lc4  = (tid & 15) * 4;

#define KV_LOAD(kt) do {                                                        \
        const int _k0 = (kt) * KT;                                              \
        const uint32_t _ks = sbase + (QP_F + ((kt) & 1) * (KS_F + VS_F)) * 4;   \
        const uint32_t _vs = _ks + KS_F * 4;                                    \
        _Pragma("unroll")                                                       \
        for (int _u = 0; _u < 2; ++_u) {                                        \
            const int _r = lrow + _u * 16;                                      \
            const int _j = _k0 + _r;                                            \
            const int _sz = (_j < NN) ? 16 : 0;                                 \
            asm volatile("cp.async.cg.shared.global [%0], [%1], 16, %2;"        \
                :: "r"(_ks + (_r * 68 + lc4) * 4),                              \
                   "l"(Kg + (size_t)_j * HD + lc4), "r"(_sz));                  \
            asm volatile("cp.async.cg.shared.global [%0], [%1], 16, %2;"        \
                :: "r"(_vs + (_r * 72 + lc4) * 4),                              \
                   "l"(Vg + (size_t)_j * HD + lc4), "r"(_sz));                  \
        }                                                                       \
        asm volatile("cp.async.commit_group;");                                 \
    } while (0)

    float oacc[8][4];
#pragma unroll
    for (int nt = 0; nt < 8; ++nt)
#pragma unroll
        for (int e = 0; e < 4; ++e) oacc[nt][e] = 0.f;
    float mrow[2] = {-1e30f, -1e30f};
    float lrow_s[2] = {0.f, 0.f};

    KV_LOAD(0);

    for (int kt = 0; kt < NKT; ++kt) {
        const int k0 = kt * KT;
        if (kt + 1 < NKT) {
            KV_LOAD(kt + 1);
            asm volatile("cp.async.wait_group 1;");
        } else {
            asm volatile("cp.async.wait_group 0;");
        }
        __syncthreads();

        const float* Ks = sm + QP_F + (kt & 1) * (KS_F + VS_F);
        const float* Vs = Ks + KS_F;

        // ---- S = Q K^T  (128 x 32) ----
        float sacc[4][4];
#pragma unroll
        for (int nt = 0; nt < 4; ++nt)
#pragma unroll
            for (int e = 0; e < 4; ++e) sacc[nt][e] = 0.f;

#pragma unroll
        for (int ks = 0; ks < 8; ++ks) {
#pragma unroll
            for (int nt = 0; nt < 4; ++nt) {
                const float* bp = Ks + (nt * 8 + tq) * 68 + ks * 8 + tr;
                uint32_t bf[2] = { __float_as_uint(bp[0]), __float_as_uint(bp[4]) };
                mma_tf32(sacc[nt], qf[ks], bf);
            }
        }

        // ---- bias add ----
#pragma unroll
        for (int nt = 0; nt < 4; ++nt) {
#pragma unroll
            for (int hh = 0; hh < 2; ++hh) {
                const int row = q0 + r0 + tq + 8 * hh;
                const int col = k0 + nt * 8 + 2 * tr;
                const float2 bb = __ldg(reinterpret_cast<const float2*>(
                    Bh + (size_t)row * BSTR + col));
                sacc[nt][2 * hh + 0] += bb.x;
                sacc[nt][2 * hh + 1] += bb.y;
            }
        }
        // ---- mask invalid keys (last tile only) ----
        if (k0 + KT > NN) {
#pragma unroll
            for (int nt = 0; nt < 4; ++nt)
#pragma unroll
                for (int e = 0; e < 4; ++e) {
                    const int col = k0 + nt * 8 + 2 * tr + (e & 1);
                    if (col >= NN) sacc[nt][e] = -1e30f;
                }
        }

        // ---- online softmax (rows tq and tq+8; quad-local reductions) ----
#pragma unroll
        for (int hh = 0; hh < 2; ++hh) {
            float mx = -1e30f;
#pragma unroll
            for (int nt = 0; nt < 4; ++nt)
                mx = fmaxf(mx, fmaxf(sacc[nt][2 * hh], sacc[nt][2 * hh + 1]));
            mx = fmaxf(mx, __shfl_xor_sync(0xffffffffu, mx, 1));
            mx = fmaxf(mx, __shfl_xor_sync(0xffffffffu, mx, 2));
            const float mnew = fmaxf(mrow[hh], mx);
            const float corr = __expf(mrow[hh] - mnew);
            mrow[hh] = mnew;
            float ps = 0.f;
#pragma unroll
            for (int nt = 0; nt < 4; ++nt) {
                const float e0 = __expf(sacc[nt][2 * hh] - mnew);
                const float e1 = __expf(sacc[nt][2 * hh + 1] - mnew);
                sacc[nt][2 * hh] = e0; sacc[nt][2 * hh + 1] = e1;
                ps += e0 + e1;
            }
            ps += __shfl_xor_sync(0xffffffffu, ps, 1);
            ps += __shfl_xor_sync(0xffffffffu, ps, 2);
            lrow_s[hh] = lrow_s[hh] * corr + ps;
#pragma unroll
            for (int nt = 0; nt < 4; ++nt) {
                oacc[nt][2 * hh] *= corr;
                oacc[nt][2 * hh + 1] *= corr;
            }
#pragma unroll
            for (int nt = 4; nt < 8; ++nt) {
                oacc[nt][2 * hh] *= corr;
                oacc[nt][2 * hh + 1] *= corr;
            }
        }

        // ---- stage P to smem (per-warp rows; warp-local hazard only) ----
#pragma unroll
        for (int nt = 0; nt < 4; ++nt) {
            *reinterpret_cast<float2*>(QP + (r0 + tq) * 68 + nt * 8 + 2 * tr) =
                make_float2(sacc[nt][0], sacc[nt][1]);
            *reinterpret_cast<float2*>(QP + (r0 + tq + 8) * 68 + nt * 8 + 2 * tr) =
                make_float2(sacc[nt][2], sacc[nt][3]);
        }
        __syncwarp();

        // ---- O += P V  (k-dim = 32) ----
#pragma unroll
        for (int ks = 0; ks < 4; ++ks) {
            const float* ap = QP + (r0 + tq) * 68 + ks * 8 + tr;
            uint32_t af[4];
            af[0] = __float_as_uint(ap[0]);
            af[1] = __float_as_uint(ap[8 * 68]);
            af[2] = __float_as_uint(ap[4]);
            af[3] = __float_as_uint(ap[8 * 68 + 4]);
#pragma unroll
            for (int nt = 0; nt < 8; ++nt) {
                const float* bp = Vs + (ks * 8 + tr) * 72 + nt * 8 + tq;
                uint32_t bf[2] = { __float_as_uint(bp[0]),
                                   __float_as_uint(bp[4 * 72]) };
                mma_tf32(oacc[nt], af, bf);
            }
        }
        __syncthreads();   // done with this K/V stage + P before reuse
    }
#undef KV_LOAD

    // ---- normalize + write g_ao (tf32-rounded) ----
#pragma unroll
    for (int hh = 0; hh < 2; ++hh) {
        const int i = q0 + r0 + tq + 8 * hh;
        if (i < NN) {
            const float inv = 1.f / lrow_s[hh];
#pragma unroll
            for (int nt = 0; nt < 8; ++nt) {
                float2 w = make_float2(oacc[nt][2 * hh] * inv,
                                       oacc[nt][2 * hh + 1] * inv);
                w.x = rna_tf32(w.x); w.y = rna_tf32(w.y);
                *reinterpret_cast<float2*>(
                    g_ao + ((size_t)b * NN + i) * CC + h * HD + nt * 8 + 2 * tr) = w;
            }
        }
    }
}

// ---------------------------------------------------------------------------
extern "C" void kernel_launch(void* const* d_in, const int* in_sizes, int n_in,
                              void* d_out, int out_size)
{
    const float* x         = (const float*)d_in[0];
    const float* qkv_w     = (const float*)d_in[1];
    const float* proj_w    = (const float*)d_in[2];
    const float* proj_b    = (const float*)d_in[3];
    const float* rel_table = (const float*)d_in[4];
    const float* g2l       = (const float*)d_in[5];
    const float* g2g       = (const float*)d_in[6];
    float* out = (float*)d_out;

    (void)in_sizes; (void)n_in; (void)out_size;

    cudaFuncSetAttribute(attn_mma,
                         cudaFuncAttributeMaxDynamicSharedMemorySize, ATTN_SMEM);
    cudaFuncSetAttribute(gemm_mma<0>,
                         cudaFuncAttributeMaxDynamicSharedMemorySize, GEMM_SMEM);
    cudaFuncSetAttribute(gemm_mma<1>,
                         cudaFuncAttributeMaxDynamicSharedMemorySize, GEMM_SMEM);

    // 0) tf32 rounding (single launch) + bias precompute
    {
        int n4 = N4X + N4Q + N4P;
        round_all<<<(n4 + 255) / 256, 256>>>(x, qkv_w, proj_w);
        dim3 gb(HH, NN);
        bias_kernel<<<gb, 256>>>(rel_table, g2l, g2g);
    }
    // 1) QKV GEMM (tf32 mma.sync)
    {
        dim3 grid(QKVN / 128, (MROWS + 127) / 128);   // (18, 99)
        gemm_mma<0><<<grid, 256, GEMM_SMEM>>>(nullptr, nullptr, MROWS);
    }
    // 2) flash attention (tf32 mma.sync, 2 CTA/SM) -> g_ao
    {
        dim3 grid((NN + 127) / 128, BB * HH);         // (7, 192)
        attn_mma<<<grid, 256, ATTN_SMEM>>>();
    }
    // 3) proj GEMM (tf32 mma.sync) + bias -> out
    {
        dim3 grid(CC / 128, (MROWS + 127) / 128);     // (6, 99)
        gemm_mma<1><<<grid, 256, GEMM_SMEM>>>(proj_b, out, MROWS);
    }
}

// round 10
// speedup vs baseline: 9.1520x; 1.0032x over previous
#include <cuda_runtime.h>
#include <cuda_bf16.h>
#include <cstdint>

// Problem constants
#define BB    16
#define NN    785
#define CC    768
#define HH    12
#define HD    64
#define MROWS (BB * NN)      // 12560
#define QKVN  (3 * CC)       // 2304
#define WXY   28
#define RELW  55
#define BROWS 896            // padded query rows for bias (7 * 128)
#define BSTR  836
#define KDIM  768
#define NCHUNK 24            // 768 / 32
#define LOG2E 1.4426950408889634f

// -------- scratch (static device arrays; no allocations allowed) ----------
__device__ float g_x32[MROWS * CC];          // x rounded to tf32
__device__ float g_wq [QKVN * CC];           // qkv_w rounded to tf32
__device__ float g_wp [CC * CC];             // proj_w rounded to tf32
__device__ float g_q  [BB * HH * NN * HD];   // [B,H,N,64], Q scaled 1/8*log2e
__device__ float g_k  [BB * HH * NN * HD];
__device__ float g_v  [BB * HH * NN * HD];
__device__ float g_ao [MROWS * CC];          // attention out (tf32-rounded)
__device__ float g_bias[HH * BROWS * BSTR];  // [h][i][j] bias*log2e (pads 0)

// ---------------------------------------------------------------------------
__device__ __forceinline__ uint32_t smem_u32(const void* p) {
    uint32_t a;
    asm("{ .reg .u64 t; cvta.to.shared.u64 t, %1; cvt.u32.u64 %0, t; }"
        : "=r"(a) : "l"(p));
    return a;
}
__device__ __forceinline__ float rna_tf32(float v) {
    uint32_t u;
    asm("cvt.rna.tf32.f32 %0, %1;" : "=r"(u) : "f"(v));
    return __uint_as_float(u);
}
__device__ __forceinline__ float ex2(float x) {
    float r;
    asm("ex2.approx.f32 %0, %1;" : "=f"(r) : "f"(x));
    return r;
}
__device__ __forceinline__ void mma_tf32(float* d, const uint32_t* a,
                                         const uint32_t* b) {
    asm volatile(
        "mma.sync.aligned.m16n8k8.row.col.f32.tf32.tf32.f32 "
        "{%0,%1,%2,%3}, {%4,%5,%6,%7}, {%8,%9}, {%0,%1,%2,%3};"
        : "+f"(d[0]), "+f"(d[1]), "+f"(d[2]), "+f"(d[3])
        : "r"(a[0]), "r"(a[1]), "r"(a[2]), "r"(a[3]), "r"(b[0]), "r"(b[1]));
}

// ---------------------------------------------------------------------------
// tf32 rounding pre-pass, all three tensors in one launch.
// ---------------------------------------------------------------------------
#define N4X (MROWS * CC / 4)
#define N4Q (QKVN * CC / 4)
#define N4P (CC * CC / 4)

__global__ void __launch_bounds__(256)
round_all(const float* __restrict__ x, const float* __restrict__ wq,
          const float* __restrict__ wp)
{
    int i = blockIdx.x * 256 + threadIdx.x;
    const float* src;
    float* dst;
    if (i < N4X)                  { src = x;  dst = g_x32; }
    else if (i < N4X + N4Q)       { src = wq; dst = g_wq;  i -= N4X; }
    else if (i < N4X + N4Q + N4P) { src = wp; dst = g_wp;  i -= N4X + N4Q; }
    else return;
    float4 v = reinterpret_cast<const float4*>(src)[i];
    v.x = rna_tf32(v.x); v.y = rna_tf32(v.y);
    v.z = rna_tf32(v.z); v.w = rna_tf32(v.w);
    reinterpret_cast<float4*>(dst)[i] = v;
}

// ---------------------------------------------------------------------------
// tf32 mma.sync NT GEMM — 3-stage cp.async, ONE sync per chunk.
// ---------------------------------------------------------------------------
#define ASTRIDE   36
#define ABLK_F    (128 * ASTRIDE)
#define STAGE_F   (2 * ABLK_F)
#define GEMM_SMEM (3 * STAGE_F * 4)      // 110592 B -> still 2 CTAs/SM

template <int MODE>
__global__ void __launch_bounds__(256, 2)
gemm_mma(const float* __restrict__ bias, float* __restrict__ Cout, int M)
{
    extern __shared__ float sm[];
    const uint32_t sbase = smem_u32(sm);

    const float* __restrict__ A  = (MODE == 0) ? g_x32 : g_ao;
    const float* __restrict__ Bm = (MODE == 0) ? g_wq  : g_wp;

    const int tid    = threadIdx.x;
    const int blockM = blockIdx.y * 128;
    const int blockN = blockIdx.x * 128;

    const int lrow  = tid >> 1;
    const int lhalf = tid & 1;
    const int arow  = blockM + lrow;
    const bool aok  = arow < M;
    const float* aptr = A  + (size_t)(aok ? arow : 0) * KDIM + lhalf * 16;
    const float* bptr = Bm + (size_t)(blockN + lrow) * KDIM + lhalf * 16;
    const uint32_t adst = sbase + (uint32_t)(lrow * ASTRIDE + lhalf * 16) * 4;
    const uint32_t bdst = adst + ABLK_F * 4;
    const int asz = aok ? 16 : 0;

#define LOADC(c) do {                                                          \
        uint32_t _so = ((c) % 3) * (STAGE_F * 4);                              \
        const float* _as = aptr + (c) * 32;                                    \
        const float* _bs = bptr + (c) * 32;                                    \
        _Pragma("unroll")                                                      \
        for (int _i = 0; _i < 4; ++_i)                                         \
            asm volatile("cp.async.cg.shared.global [%0], [%1], 16, %2;"       \
                :: "r"(adst + _so + _i * 16), "l"(_as + _i * 4), "r"(asz));    \
        _Pragma("unroll")                                                      \
        for (int _i = 0; _i < 4; ++_i)                                         \
            asm volatile("cp.async.cg.shared.global [%0], [%1], 16, 16;"       \
                :: "r"(bdst + _so + _i * 16), "l"(_bs + _i * 4));              \
        asm volatile("cp.async.commit_group;");                                \
    } while (0)

    const int lane  = tid & 31;
    const int wid   = tid >> 5;
    const int warpM = (wid & 3) * 32;
    const int warpN = (wid >> 2) * 64;
    const int tq    = lane >> 2;
    const int tr    = lane & 3;

    float acc[2][8][4];
#pragma unroll
    for (int mt = 0; mt < 2; ++mt)
#pragma unroll
        for (int nt = 0; nt < 8; ++nt)
#pragma unroll
            for (int e = 0; e < 4; ++e) acc[mt][nt][e] = 0.f;

    LOADC(0);
    LOADC(1);

    for (int c = 0; c < NCHUNK; ++c) {
        // wait until chunk c's data is in smem
        if (c + 1 < NCHUNK) asm volatile("cp.async.wait_group 1;");
        else                asm volatile("cp.async.wait_group 0;");
        __syncthreads();   // all warps see chunk c; all done computing c-1
        if (c + 2 < NCHUNK) LOADC(c + 2);   // overwrites buf read at c-1: safe

        const float* As = sm + (c % 3) * STAGE_F;
        const float* Bs = As + ABLK_F;

#pragma unroll
        for (int ks = 0; ks < 4; ++ks) {
            const int k0 = ks * 8;
            uint32_t af[2][4];
#pragma unroll
            for (int mt = 0; mt < 2; ++mt) {
                const float* ap = As + (warpM + mt * 16 + tq) * ASTRIDE + k0 + tr;
                af[mt][0] = __float_as_uint(ap[0]);
                af[mt][1] = __float_as_uint(ap[8 * ASTRIDE]);
                af[mt][2] = __float_as_uint(ap[4]);
                af[mt][3] = __float_as_uint(ap[8 * ASTRIDE + 4]);
            }
#pragma unroll
            for (int nt = 0; nt < 8; ++nt) {
                const float* bp = Bs + (warpN + nt * 8 + tq) * ASTRIDE + k0 + tr;
                uint32_t bf[2] = { __float_as_uint(bp[0]), __float_as_uint(bp[4]) };
#pragma unroll
                for (int mt = 0; mt < 2; ++mt)
                    mma_tf32(acc[mt][nt], af[mt], bf);
            }
        }
    }
#undef LOADC

#pragma unroll
    for (int mt = 0; mt < 2; ++mt) {
#pragma unroll
        for (int half = 0; half < 2; ++half) {
            const int row = blockM + warpM + mt * 16 + tq + half * 8;
            if (row >= M) continue;
            int b = 0, n = 0;
            if (MODE == 0) { b = row / NN; n = row - b * NN; }
#pragma unroll
            for (int nt = 0; nt < 8; ++nt) {
                const int col = blockN + warpN + nt * 8 + tr * 2;
                const float vx = acc[mt][nt][half * 2 + 0];
                const float vy = acc[mt][nt][half * 2 + 1];
                if (MODE == 0) {
                    const int s   = col / CC;
                    const int rem = col - s * CC;
                    const int h   = rem >> 6;
                    const int d   = rem & 63;
                    // Q carries 1/8 * log2e for base-2 softmax
                    const float scl = (s == 0) ? (0.125f * LOG2E) : 1.f;
                    float* dp = (s == 0 ? g_q : (s == 1 ? g_k : g_v)) +
                                (((size_t)b * HH + h) * NN + n) * HD + d;
                    *reinterpret_cast<float2*>(dp) = make_float2(vx * scl, vy * scl);
                } else {
                    *reinterpret_cast<float2*>(Cout + (size_t)row * CC + col) =
                        make_float2(vx + bias[col], vy + bias[col + 1]);
                }
            }
        }
    }
}

// ---------------------------------------------------------------------------
// Bias precompute, pre-scaled by log2e (rows 0..784; pad rows stay zero)
// ---------------------------------------------------------------------------
__global__ void __launch_bounds__(256)
bias_kernel(const float* __restrict__ rel_table,
            const float* __restrict__ g2l,
            const float* __restrict__ g2g)
{
    const int h = blockIdx.x;
    const int i = blockIdx.y;
    float* row = g_bias + ((size_t)h * BROWS + i) * BSTR;
    const int xi = (i - 1) / WXY, yi = (i - 1) % WXY;
    for (int j = threadIdx.x; j < NN; j += 256) {
        float v;
        if (i == 0)      v = (j == 0) ? g2g[h] : g2l[h];
        else if (j == 0) v = g2l[HH + h];
        else {
            int xj = (j - 1) / WXY, yj = (j - 1) % WXY;
            int idx = (xi - xj + (WXY - 1)) * RELW + (yi - yj + (WXY - 1));
            v = rel_table[idx * HH + h];
        }
        row[j] = v * LOG2E;
    }
}

// ---------------------------------------------------------------------------
// Flash attention on mma.sync tf32.  KT=32, 3-stage cp.async KV pipeline,
// ONE __syncthreads per tile, base-2 softmax (ex2.approx).
// ---------------------------------------------------------------------------
#define KT     32
#define NKT    25                         // ceil(785/32)
#define QP_F   (128 * 68)                 // 8704
#define KS_F   (KT * 68)                  // 2176
#define VS_F   (KT * 72)                  // 2304
#define ATTN_SMEM ((QP_F + 3 * (KS_F + VS_F)) * 4)   // 88576 B -> 2 CTA/SM

__global__ void __launch_bounds__(256, 2)
attn_mma()
{
    extern __shared__ float sm[];
    float* QP = sm;                       // Q staging, then P (per-warp rows)
    const uint32_t sbase = smem_u32(sm);

    const int bh = blockIdx.y;
    const int b  = bh / HH;
    const int h  = bh - b * HH;
    const int q0 = blockIdx.x * 128;

    const int tid  = threadIdx.x;
    const int lane = tid & 31;
    const int wid  = tid >> 5;
    const int tq   = lane >> 2;
    const int tr   = lane & 3;
    const int r0   = wid * 16;

    const float* Qg = g_q + (size_t)bh * NN * HD;
    const float* Kg = g_k + (size_t)bh * NN * HD;
    const float* Vg = g_v + (size_t)bh * NN * HD;
    const float* Bh = g_bias + (size_t)h * BROWS * BSTR;

    // ---- stage Q tile [128][64] into QP (stride 68) ----
#pragma unroll
    for (int u = 0; u < 8; ++u) {
        const int lin = tid + u * 256;
        const int row = lin >> 4;
        const int c4  = (lin & 15) * 4;
        const int gi  = q0 + row;
        float4 v = make_float4(0.f, 0.f, 0.f, 0.f);
        if (gi < NN) v = *reinterpret_cast<const float4*>(Qg + (size_t)gi * HD + c4);
        *reinterpret_cast<float4*>(QP + row * 68 + c4) = v;
    }
    __syncthreads();

    // ---- Q A-fragments to registers (loop-invariant) ----
    uint32_t qf[8][4];
#pragma unroll
    for (int ks = 0; ks < 8; ++ks) {
        const float* ap = QP + (r0 + tq) * 68 + ks * 8 + tr;
        qf[ks][0] = __float_as_uint(ap[0]);
        qf[ks][1] = __float_as_uint(ap[8 * 68]);
        qf[ks][2] = __float_as_uint(ap[4]);
        qf[ks][3] = __float_as_uint(ap[8 * 68 + 4]);
    }
    __syncthreads();    // QP now free -> P buffer

    // ---- K/V cp.async mapping: 32 rows x 64B; 2 x 16B per thread each ----
    const int lrow = tid >> 4;            // 0..15
    const int lc4  = (tid & 15) * 4;

#define KV_LOAD(kt) do {                                                        \
        const int _k0 = (kt) * KT;                                              \
        const uint32_t _ks = sbase + (QP_F + ((kt) % 3) * (KS_F + VS_F)) * 4;   \
        const uint32_t _vs = _ks + KS_F * 4;                                    \
        _Pragma("unroll")                                                       \
        for (int _u = 0; _u < 2; ++_u) {                                        \
            const int _r = lrow + _u * 16;                                      \
            const int _j = _k0 + _r;                                            \
            const int _sz = (_j < NN) ? 16 : 0;                                 \
            asm volatile("cp.async.cg.shared.global [%0], [%1], 16, %2;"        \
                :: "r"(_ks + (_r * 68 + lc4) * 4),                              \
                   "l"(Kg + (size_t)_j * HD + lc4), "r"(_sz));                  \
            asm volatile("cp.async.cg.shared.global [%0], [%1], 16, %2;"        \
                :: "r"(_vs + (_r * 72 + lc4) * 4),                              \
                   "l"(Vg + (size_t)_j * HD + lc4), "r"(_sz));                  \
        }                                                                       \
        asm volatile("cp.async.commit_group;");                                 \
    } while (0)

    float oacc[8][4];
#pragma unroll
    for (int nt = 0; nt < 8; ++nt)
#pragma unroll
        for (int e = 0; e < 4; ++e) oacc[nt][e] = 0.f;
    float mrow[2] = {-1e30f, -1e30f};
    float lrow_s[2] = {0.f, 0.f};

    KV_LOAD(0);
    KV_LOAD(1);

    for (int kt = 0; kt < NKT; ++kt) {
        const int k0 = kt * KT;
        if (kt + 1 < NKT) asm volatile("cp.async.wait_group 1;");
        else              asm volatile("cp.async.wait_group 0;");
        __syncthreads();   // tile kt visible; all warps done with tile kt-1
        if (kt + 2 < NKT) KV_LOAD(kt + 2);  // overwrites buf read at kt-1: safe

        const float* Ks = sm + QP_F + (kt % 3) * (KS_F + VS_F);
        const float* Vs = Ks + KS_F;

        // ---- S = Q K^T  (128 x 32) ----
        float sacc[4][4];
#pragma unroll
        for (int nt = 0; nt < 4; ++nt)
#pragma unroll
            for (int e = 0; e < 4; ++e) sacc[nt][e] = 0.f;

#pragma unroll
        for (int ks = 0; ks < 8; ++ks) {
#pragma unroll
            for (int nt = 0; nt < 4; ++nt) {
                const float* bp = Ks + (nt * 8 + tq) * 68 + ks * 8 + tr;
                uint32_t bf[2] = { __float_as_uint(bp[0]), __float_as_uint(bp[4]) };
                mma_tf32(sacc[nt], qf[ks], bf);
            }
        }

        // ---- bias add (already log2e-scaled) ----
#pragma unroll
        for (int nt = 0; nt < 4; ++nt) {
#pragma unroll
            for (int hh = 0; hh < 2; ++hh) {
                const int row = q0 + r0 + tq + 8 * hh;
                const int col = k0 + nt * 8 + 2 * tr;
                const float2 bb = __ldg(reinterpret_cast<const float2*>(
                    Bh + (size_t)row * BSTR + col));
                sacc[nt][2 * hh + 0] += bb.x;
                sacc[nt][2 * hh + 1] += bb.y;
            }
        }
        // ---- mask invalid keys (last tile only) ----
        if (k0 + KT > NN) {
#pragma unroll
            for (int nt = 0; nt < 4; ++nt)
#pragma unroll
                for (int e = 0; e < 4; ++e) {
                    const int col = k0 + nt * 8 + 2 * tr + (e & 1);
                    if (col >= NN) sacc[nt][e] = -1e30f;
                }
        }

        // ---- online softmax, base 2 (rows tq, tq+8; quad-local) ----
#pragma unroll
        for (int hh = 0; hh < 2; ++hh) {
            float mx = -1e30f;
#pragma unroll
            for (int nt = 0; nt < 4; ++nt)
                mx = fmaxf(mx, fmaxf(sacc[nt][2 * hh], sacc[nt][2 * hh + 1]));
            mx = fmaxf(mx, __shfl_xor_sync(0xffffffffu, mx, 1));
            mx = fmaxf(mx, __shfl_xor_sync(0xffffffffu, mx, 2));
            const float mnew = fmaxf(mrow[hh], mx);
            const float corr = ex2(mrow[hh] - mnew);
            mrow[hh] = mnew;
            float ps = 0.f;
#pragma unroll
            for (int nt = 0; nt < 4; ++nt) {
                const float e0 = ex2(sacc[nt][2 * hh] - mnew);
                const float e1 = ex2(sacc[nt][2 * hh + 1] - mnew);
                sacc[nt][2 * hh] = e0; sacc[nt][2 * hh + 1] = e1;
                ps += e0 + e1;
            }
            ps += __shfl_xor_sync(0xffffffffu, ps, 1);
            ps += __shfl_xor_sync(0xffffffffu, ps, 2);
            lrow_s[hh] = lrow_s[hh] * corr + ps;
#pragma unroll
            for (int nt = 0; nt < 8; ++nt) {
                oacc[nt][2 * hh] *= corr;
                oacc[nt][2 * hh + 1] *= corr;
            }
        }

        // ---- stage P to smem (per-warp rows; warp-local hazard only) ----
#pragma unroll
        for (int nt = 0; nt < 4; ++nt) {
            *reinterpret_cast<float2*>(QP + (r0 + tq) * 68 + nt * 8 + 2 * tr) =
                make_float2(sacc[nt][0], sacc[nt][1]);
            *reinterpret_cast<float2*>(QP + (r0 + tq + 8) * 68 + nt * 8 + 2 * tr) =
                make_float2(sacc[nt][2], sacc[nt][3]);
        }
        __syncwarp();

        // ---- O += P V  (k-dim = 32) ----
#pragma unroll
        for (int ks = 0; ks < 4; ++ks) {
            const float* ap = QP + (r0 + tq) * 68 + ks * 8 + tr;
            uint32_t af[4];
            af[0] = __float_as_uint(ap[0]);
            af[1] = __float_as_uint(ap[8 * 68]);
            af[2] = __float_as_uint(ap[4]);
            af[3] = __float_as_uint(ap[8 * 68 + 4]);
#pragma unroll
            for (int nt = 0; nt < 8; ++nt) {
                const float* bp = Vs + (ks * 8 + tr) * 72 + nt * 8 + tq;
                uint32_t bf[2] = { __float_as_uint(bp[0]),
                                   __float_as_uint(bp[4 * 72]) };
                mma_tf32(oacc[nt], af, bf);
            }
        }
        // no end-of-loop sync: next iteration's single sync covers reuse
    }
#undef KV_LOAD

    // ---- normalize + write g_ao (tf32-rounded) ----
#pragma unroll
    for (int hh = 0; hh < 2; ++hh) {
        const int i = q0 + r0 + tq + 8 * hh;
        if (i < NN) {
            const float inv = 1.f / lrow_s[hh];
#pragma unroll
            for (int nt = 0; nt < 8; ++nt) {
                float2 w = make_float2(oacc[nt][2 * hh] * inv,
                                       oacc[nt][2 * hh + 1] * inv);
                w.x = rna_tf32(w.x); w.y = rna_tf32(w.y);
                *reinterpret_cast<float2*>(
                    g_ao + ((size_t)b * NN + i) * CC + h * HD + nt * 8 + 2 * tr) = w;
            }
        }
    }
}

// ---------------------------------------------------------------------------
extern "C" void kernel_launch(void* const* d_in, const int* in_sizes, int n_in,
                              void* d_out, int out_size)
{
    const float* x         = (const float*)d_in[0];
    const float* qkv_w     = (const float*)d_in[1];
    const float* proj_w    = (const float*)d_in[2];
    const float* proj_b    = (const float*)d_in[3];
    const float* rel_table = (const float*)d_in[4];
    const float* g2l       = (const float*)d_in[5];
    const float* g2g       = (const float*)d_in[6];
    float* out = (float*)d_out;

    (void)in_sizes; (void)n_in; (void)out_size;

    cudaFuncSetAttribute(attn_mma,
                         cudaFuncAttributeMaxDynamicSharedMemorySize, ATTN_SMEM);
    cudaFuncSetAttribute(gemm_mma<0>,
                         cudaFuncAttributeMaxDynamicSharedMemorySize, GEMM_SMEM);
    cudaFuncSetAttribute(gemm_mma<1>,
                         cudaFuncAttributeMaxDynamicSharedMemorySize, GEMM_SMEM);

    // 0) tf32 rounding (single launch) + bias precompute
    {
        int n4 = N4X + N4Q + N4P;
        round_all<<<(n4 + 255) / 256, 256>>>(x, qkv_w, proj_w);
        dim3 gb(HH, NN);
        bias_kernel<<<gb, 256>>>(rel_table, g2l, g2g);
    }
    // 1) QKV GEMM (tf32 mma.sync, 3-stage)
    {
        dim3 grid(QKVN / 128, (MROWS + 127) / 128);   // (18, 99)
        gemm_mma<0><<<grid, 256, GEMM_SMEM>>>(nullptr, nullptr, MROWS);
    }
    // 2) flash attention (tf32 mma.sync, 3-stage, 2 CTA/SM) -> g_ao
    {
        dim3 grid((NN + 127) / 128, BB * HH);         // (7, 192)
        attn_mma<<<grid, 256, ATTN_SMEM>>>();
    }
    // 3) proj GEMM (tf32 mma.sync, 3-stage) + bias -> out
    {
        dim3 grid(CC / 128, (MROWS + 127) / 128);     // (6, 99)
        gemm_mma<1><<<grid, 256, GEMM_SMEM>>>(proj_b, out, MROWS);
    }
}

// round 12
// speedup vs baseline: 10.0146x; 1.0943x over previous
#include <cuda_runtime.h>
#include <cuda_bf16.h>
#include <cstdint>

// Problem constants
#define BB    16
#define NN    785
#define CC    768
#define HH    12
#define HD    64
#define MROWS (BB * NN)      // 12560
#define QKVN  (3 * CC)       // 2304
#define WXY   28
#define RELW  55
#define BROWS 896            // padded query rows for bias (7 * 128)
#define BSTR  836
#define KDIM  768
#define NCHUNK 24            // 768 / 32
#define LOG2E 1.4426950408889634f

// -------- scratch (static device arrays; no allocations allowed) ----------
__device__ float g_x32[MROWS * CC];          // x rounded to tf32
__device__ float g_wq [QKVN * CC];           // qkv_w rounded to tf32
__device__ float g_wp [CC * CC];             // proj_w rounded to tf32
__device__ float g_q  [BB * HH * NN * HD];   // [B,H,N,64], Q scaled 1/8*log2e
__device__ float g_k  [BB * HH * NN * HD];
__device__ float g_v  [BB * HH * NN * HD];
__device__ float g_ao [MROWS * CC];          // attention out (tf32-rounded)
__device__ float g_bias[HH * BROWS * BSTR];  // [h][i][j] bias*log2e (pads 0)

// ---------------------------------------------------------------------------
__device__ __forceinline__ uint32_t smem_u32(const void* p) {
    uint32_t a;
    asm("{ .reg .u64 t; cvta.to.shared.u64 t, %1; cvt.u32.u64 %0, t; }"
        : "=r"(a) : "l"(p));
    return a;
}
__device__ __forceinline__ float rna_tf32(float v) {
    uint32_t u;
    asm("cvt.rna.tf32.f32 %0, %1;" : "=r"(u) : "f"(v));
    return __uint_as_float(u);
}
__device__ __forceinline__ float ex2(float x) {
    float r;
    asm("ex2.approx.f32 %0, %1;" : "=f"(r) : "f"(x));
    return r;
}
__device__ __forceinline__ void mma_tf32(float* d, const uint32_t* a,
                                         const uint32_t* b) {
    asm volatile(
        "mma.sync.aligned.m16n8k8.row.col.f32.tf32.tf32.f32 "
        "{%0,%1,%2,%3}, {%4,%5,%6,%7}, {%8,%9}, {%0,%1,%2,%3};"
        : "+f"(d[0]), "+f"(d[1]), "+f"(d[2]), "+f"(d[3])
        : "r"(a[0]), "r"(a[1]), "r"(a[2]), "r"(a[3]), "r"(b[0]), "r"(b[1]));
}
// ldmatrix x4: one call = one tf32 A-fragment (m16k8) or two B-fragments (n8k8)
__device__ __forceinline__ void ldsm4(uint32_t* r, uint32_t addr) {
    asm volatile(
        "ldmatrix.sync.aligned.m8n8.x4.shared.b16 {%0,%1,%2,%3}, [%4];"
        : "=r"(r[0]), "=r"(r[1]), "=r"(r[2]), "=r"(r[3]) : "r"(addr));
}

// ---------------------------------------------------------------------------
// tf32 rounding pre-pass, all three tensors in one launch.
// ---------------------------------------------------------------------------
#define N4X (MROWS * CC / 4)
#define N4Q (QKVN * CC / 4)
#define N4P (CC * CC / 4)

__global__ void __launch_bounds__(256)
round_all(const float* __restrict__ x, const float* __restrict__ wq,
          const float* __restrict__ wp)
{
    int i = blockIdx.x * 256 + threadIdx.x;
    const float* src;
    float* dst;
    if (i < N4X)                  { src = x;  dst = g_x32; }
    else if (i < N4X + N4Q)       { src = wq; dst = g_wq;  i -= N4X; }
    else if (i < N4X + N4Q + N4P) { src = wp; dst = g_wp;  i -= N4X + N4Q; }
    else return;
    float4 v = reinterpret_cast<const float4*>(src)[i];
    v.x = rna_tf32(v.x); v.y = rna_tf32(v.y);
    v.z = rna_tf32(v.z); v.w = rna_tf32(v.w);
    reinterpret_cast<float4*>(dst)[i] = v;
}

// ---------------------------------------------------------------------------
// tf32 mma.sync NT GEMM — 3-stage cp.async, one sync per chunk,
// fragments via ldmatrix.b16 (A: 2 ldsm/ks, B: 4 ldsm/ks).
// ---------------------------------------------------------------------------
#define ASTRIDE   36
#define ABLK_F    (128 * ASTRIDE)
#define STAGE_F   (2 * ABLK_F)
#define GEMM_SMEM (3 * STAGE_F * 4)      // 110592 B -> 2 CTAs/SM

template <int MODE>
__global__ void __launch_bounds__(256, 2)
gemm_mma(const float* __restrict__ bias, float* __restrict__ Cout, int M)
{
    extern __shared__ float sm[];
    const uint32_t sbase = smem_u32(sm);

    const float* __restrict__ A  = (MODE == 0) ? g_x32 : g_ao;
    const float* __restrict__ Bm = (MODE == 0) ? g_wq  : g_wp;

    const int tid    = threadIdx.x;
    const int blockM = blockIdx.y * 128;
    const int blockN = blockIdx.x * 128;

    const int lrow  = tid >> 1;
    const int lhalf = tid & 1;
    const int arow  = blockM + lrow;
    const bool aok  = arow < M;
    const float* aptr = A  + (size_t)(aok ? arow : 0) * KDIM + lhalf * 16;
    const float* bptr = Bm + (size_t)(blockN + lrow) * KDIM + lhalf * 16;
    const uint32_t adst = sbase + (uint32_t)(lrow * ASTRIDE + lhalf * 16) * 4;
    const uint32_t bdst = adst + ABLK_F * 4;
    const int asz = aok ? 16 : 0;

#define LOADC(c) do {                                                          \
        uint32_t _so = ((c) % 3) * (STAGE_F * 4);                              \
        const float* _as = aptr + (c) * 32;                                    \
        const float* _bs = bptr + (c) * 32;                                    \
        _Pragma("unroll")                                                      \
        for (int _i = 0; _i < 4; ++_i)                                         \
            asm volatile("cp.async.cg.shared.global [%0], [%1], 16, %2;"       \
                :: "r"(adst + _so + _i * 16), "l"(_as + _i * 4), "r"(asz));    \
        _Pragma("unroll")                                                      \
        for (int _i = 0; _i < 4; ++_i)                                         \
            asm volatile("cp.async.cg.shared.global [%0], [%1], 16, 16;"       \
                :: "r"(bdst + _so + _i * 16), "l"(_bs + _i * 4));              \
        asm volatile("cp.async.commit_group;");                                \
    } while (0)

    const int lane  = tid & 31;
    const int wid   = tid >> 5;
    const int warpM = (wid & 3) * 32;
    const int warpN = (wid >> 2) * 64;
    const int tq    = lane >> 2;
    const int tr    = lane & 3;

    // ldmatrix per-lane row bases (byte offsets within a stage)
    const int lj = lane >> 3;            // matrix index 0..3
    const int lr = lane & 7;             // row within matrix
    // A matrices: [m-lo left][m-hi left][m-lo right][m-hi right]
    const uint32_t aoff =
        (uint32_t)((warpM + ((lj & 1) << 3) + lr) * ASTRIDE + ((lj >> 1) << 2)) * 4;
    // B matrices: [nt0 left][nt0 right][nt1 left][nt1 right]
    const uint32_t boff = (uint32_t)ABLK_F * 4 +
        (uint32_t)((warpN + ((lj >> 1) << 3) + lr) * ASTRIDE + ((lj & 1) << 2)) * 4;

    float acc[2][8][4];
#pragma unroll
    for (int mt = 0; mt < 2; ++mt)
#pragma unroll
        for (int nt = 0; nt < 8; ++nt)
#pragma unroll
            for (int e = 0; e < 4; ++e) acc[mt][nt][e] = 0.f;

    LOADC(0);
    LOADC(1);

    for (int c = 0; c < NCHUNK; ++c) {
        if (c + 1 < NCHUNK) asm volatile("cp.async.wait_group 1;");
        else                asm volatile("cp.async.wait_group 0;");
        __syncthreads();   // all warps see chunk c; all done computing c-1
        if (c + 2 < NCHUNK) LOADC(c + 2);

        const uint32_t stg = sbase + (uint32_t)((c % 3) * STAGE_F * 4);

#pragma unroll
        for (int ks = 0; ks < 4; ++ks) {
            uint32_t af[2][4];
#pragma unroll
            for (int mt = 0; mt < 2; ++mt)
                ldsm4(af[mt], stg + aoff +
                      (uint32_t)((mt * 16 * ASTRIDE + ks * 8) * 4));
            uint32_t bf[4][4];
#pragma unroll
            for (int p = 0; p < 4; ++p)
                ldsm4(bf[p], stg + boff +
                      (uint32_t)((p * 16 * ASTRIDE + ks * 8) * 4));
#pragma unroll
            for (int p = 0; p < 4; ++p)
#pragma unroll
                for (int mt = 0; mt < 2; ++mt) {
                    mma_tf32(acc[mt][2 * p],     af[mt], &bf[p][0]);
                    mma_tf32(acc[mt][2 * p + 1], af[mt], &bf[p][2]);
                }
        }
    }
#undef LOADC

#pragma unroll
    for (int mt = 0; mt < 2; ++mt) {
#pragma unroll
        for (int half = 0; half < 2; ++half) {
            const int row = blockM + warpM + mt * 16 + tq + half * 8;
            if (row >= M) continue;
            int b = 0, n = 0;
            if (MODE == 0) { b = row / NN; n = row - b * NN; }
#pragma unroll
            for (int nt = 0; nt < 8; ++nt) {
                const int col = blockN + warpN + nt * 8 + tr * 2;
                const float vx = acc[mt][nt][half * 2 + 0];
                const float vy = acc[mt][nt][half * 2 + 1];
                if (MODE == 0) {
                    const int s   = col / CC;
                    const int rem = col - s * CC;
                    const int h   = rem >> 6;
                    const int d   = rem & 63;
                    const float scl = (s == 0) ? (0.125f * LOG2E) : 1.f;
                    float* dp = (s == 0 ? g_q : (s == 1 ? g_k : g_v)) +
                                (((size_t)b * HH + h) * NN + n) * HD + d;
                    *reinterpret_cast<float2*>(dp) = make_float2(vx * scl, vy * scl);
                } else {
                    *reinterpret_cast<float2*>(Cout + (size_t)row * CC + col) =
                        make_float2(vx + bias[col], vy + bias[col + 1]);
                }
            }
        }
    }
}

// ---------------------------------------------------------------------------
// Bias precompute, pre-scaled by log2e (rows 0..784; pad rows stay zero)
// ---------------------------------------------------------------------------
__global__ void __launch_bounds__(256)
bias_kernel(const float* __restrict__ rel_table,
            const float* __restrict__ g2l,
            const float* __restrict__ g2g)
{
    const int h = blockIdx.x;
    const int i = blockIdx.y;
    float* row = g_bias + ((size_t)h * BROWS + i) * BSTR;
    const int xi = (i - 1) / WXY, yi = (i - 1) % WXY;
    for (int j = threadIdx.x; j < NN; j += 256) {
        float v;
        if (i == 0)      v = (j == 0) ? g2g[h] : g2l[h];
        else if (j == 0) v = g2l[HH + h];
        else {
            int xj = (j - 1) / WXY, yj = (j - 1) % WXY;
            int idx = (xi - xj + (WXY - 1)) * RELW + (yi - yj + (WXY - 1));
            v = rel_table[idx * HH + h];
        }
        row[j] = v * LOG2E;
    }
}

// ---------------------------------------------------------------------------
// Flash attention on mma.sync tf32.  KT=32, 3-stage cp.async, one sync/tile,
// base-2 softmax; K and P fragments via ldmatrix.b16.
// ---------------------------------------------------------------------------
#define KT     32
#define NKT    25                         // ceil(785/32)
#define QP_F   (128 * 68)                 // 8704
#define KS_F   (KT * 68)                  // 2176
#define VS_F   (KT * 72)                  // 2304
#define ATTN_SMEM ((QP_F + 3 * (KS_F + VS_F)) * 4)   // 88576 B -> 2 CTA/SM

__global__ void __launch_bounds__(256, 2)
attn_mma()
{
    extern __shared__ float sm[];
    float* QP = sm;                       // Q staging, then P (per-warp rows)
    const uint32_t sbase = smem_u32(sm);

    const int bh = blockIdx.y;
    const int b  = bh / HH;
    const int h  = bh - b * HH;
    const int q0 = blockIdx.x * 128;

    const int tid  = threadIdx.x;
    const int lane = tid & 31;
    const int wid  = tid >> 5;
    const int tq   = lane >> 2;
    const int tr   = lane & 3;
    const int r0   = wid * 16;

    const float* Qg = g_q + (size_t)bh * NN * HD;
    const float* Kg = g_k + (size_t)bh * NN * HD;
    const float* Vg = g_v + (size_t)bh * NN * HD;
    const float* Bh = g_bias + (size_t)h * BROWS * BSTR;

    // ldmatrix per-lane row bases
    const int lj = lane >> 3;
    const int lr = lane & 7;
    // K (B-type): [nt0 left][nt0 right][nt1 left][nt1 right], stride 68
    const uint32_t koff =
        (uint32_t)(((((lj >> 1) << 3) + lr) * 68) + ((lj & 1) << 2)) * 4;
    // P (A-type): [r-lo left][r-hi left][r-lo right][r-hi right], stride 68
    const uint32_t poff =
        (uint32_t)(((r0 + ((lj & 1) << 3) + lr) * 68) + ((lj >> 1) << 2)) * 4;

    // ---- stage Q tile [128][64] into QP (stride 68) ----
#pragma unroll
    for (int u = 0; u < 8; ++u) {
        const int lin = tid + u * 256;
        const int row = lin >> 4;
        const int c4  = (lin & 15) * 4;
        const int gi  = q0 + row;
        float4 v = make_float4(0.f, 0.f, 0.f, 0.f);
        if (gi < NN) v = *reinterpret_cast<const float4*>(Qg + (size_t)gi * HD + c4);
        *reinterpret_cast<float4*>(QP + row * 68 + c4) = v;
    }
    __syncthreads();

    // ---- Q A-fragments to registers (loop-invariant; via ldmatrix) ----
    uint32_t qf[8][4];
#pragma unroll
    for (int ks = 0; ks < 8; ++ks)
        ldsm4(qf[ks], sbase + poff + (uint32_t)(ks * 8 * 4));
    __syncthreads();    // QP now free -> P buffer

    // ---- K/V cp.async mapping: 32 rows x 64B; 2 x 16B per thread each ----
    const int lrow = tid >> 4;            // 0..15
    const int lc4  = (tid & 15) * 4;

#define KV_LOAD(kt) do {                                                        \
        const int _k0 = (kt) * KT;                                              \
        const uint32_t _ks = sbase + (QP_F + ((kt) % 3) * (KS_F + VS_F)) * 4;   \
        const uint32_t _vs = _ks + KS_F * 4;                                    \
        _Pragma("unroll")                                                       \
        for (int _u = 0; _u < 2; ++_u) {                                        \
            const int _r = lrow + _u * 16;                                      \
            const int _j = _k0 + _r;                                            \
            const int _sz = (_j < NN) ? 16 : 0;                                 \
            asm volatile("cp.async.cg.shared.global [%0], [%1], 16, %2;"        \
                :: "r"(_ks + (_r * 68 + lc4) * 4),                              \
                   "l"(Kg + (size_t)_j * HD + lc4), "r"(_sz));                  \
            asm volatile("cp.async.cg.shared.global [%0], [%1], 16, %2;"        \
                :: "r"(_vs + (_r * 72 + lc4) * 4),                              \
                   "l"(Vg + (size_t)_j * HD + lc4), "r"(_sz));                  \
        }                                                                       \
        asm volatile("cp.async.commit_group;");                                 \
    } while (0)

    float oacc[8][4];
#pragma unroll
    for (int nt = 0; nt < 8; ++nt)
#pragma unroll
        for (int e = 0; e < 4; ++e) oacc[nt][e] = 0.f;
    float mrow[2] = {-1e30f, -1e30f};
    float lrow_s[2] = {0.f, 0.f};

    KV_LOAD(0);
    KV_LOAD(1);

    for (int kt = 0; kt < NKT; ++kt) {
        const int k0 = kt * KT;
        if (kt + 1 < NKT) asm volatile("cp.async.wait_group 1;");
        else              asm volatile("cp.async.wait_group 0;");
        __syncthreads();   // tile kt visible; all warps done with tile kt-1
        if (kt + 2 < NKT) KV_LOAD(kt + 2);

        const uint32_t ksAddr = sbase + (QP_F + (kt % 3) * (KS_F + VS_F)) * 4;
        const float*   Vs     = sm + QP_F + (kt % 3) * (KS_F + VS_F) + KS_F;

        // ---- S = Q K^T  (128 x 32), K fragments via ldmatrix ----
        float sacc[4][4];
#pragma unroll
        for (int nt = 0; nt < 4; ++nt)
#pragma unroll
            for (int e = 0; e < 4; ++e) sacc[nt][e] = 0.f;

#pragma unroll
        for (int ks = 0; ks < 8; ++ks) {
            uint32_t bk[2][4];
#pragma unroll
            for (int p = 0; p < 2; ++p)
                ldsm4(bk[p], ksAddr + koff +
                      (uint32_t)((p * 16 * 68 + ks * 8) * 4));
#pragma unroll
            for (int p = 0; p < 2; ++p) {
                mma_tf32(sacc[2 * p],     qf[ks], &bk[p][0]);
                mma_tf32(sacc[2 * p + 1], qf[ks], &bk[p][2]);
            }
        }

        // ---- bias add (already log2e-scaled) ----
#pragma unroll
        for (int nt = 0; nt < 4; ++nt) {
#pragma unroll
            for (int hh = 0; hh < 2; ++hh) {
                const int row = q0 + r0 + tq + 8 * hh;
                const int col = k0 + nt * 8 + 2 * tr;
                const float2 bb = __ldg(reinterpret_cast<const float2*>(
                    Bh + (size_t)row * BSTR + col));
                sacc[nt][2 * hh + 0] += bb.x;
                sacc[nt][2 * hh + 1] += bb.y;
            }
        }
        // ---- mask invalid keys (last tile only) ----
        if (k0 + KT > NN) {
#pragma unroll
            for (int nt = 0; nt < 4; ++nt)
#pragma unroll
                for (int e = 0; e < 4; ++e) {
                    const int col = k0 + nt * 8 + 2 * tr + (e & 1);
                    if (col >= NN) sacc[nt][e] = -1e30f;
                }
        }

        // ---- online softmax, base 2 (rows tq, tq+8; quad-local) ----
#pragma unroll
        for (int hh = 0; hh < 2; ++hh) {
            float mx = -1e30f;
#pragma unroll
            for (int nt = 0; nt < 4; ++nt)
                mx = fmaxf(mx, fmaxf(sacc[nt][2 * hh], sacc[nt][2 * hh + 1]));
            mx = fmaxf(mx, __shfl_xor_sync(0xffffffffu, mx, 1));
            mx = fmaxf(mx, __shfl_xor_sync(0xffffffffu, mx, 2));
            const float mnew = fmaxf(mrow[hh], mx);
            const float corr = ex2(mrow[hh] - mnew);
            mrow[hh] = mnew;
            float ps = 0.f;
#pragma unroll
            for (int nt = 0; nt < 4; ++nt) {
                const float e0 = ex2(sacc[nt][2 * hh] - mnew);
                const float e1 = ex2(sacc[nt][2 * hh + 1] - mnew);
                sacc[nt][2 * hh] = e0; sacc[nt][2 * hh + 1] = e1;
                ps += e0 + e1;
            }
            ps += __shfl_xor_sync(0xffffffffu, ps, 1);
            ps += __shfl_xor_sync(0xffffffffu, ps, 2);
            lrow_s[hh] = lrow_s[hh] * corr + ps;
#pragma unroll
            for (int nt = 0; nt < 8; ++nt) {
                oacc[nt][2 * hh] *= corr;
                oacc[nt][2 * hh + 1] *= corr;
            }
        }

        // ---- stage P to smem (per-warp rows; warp-local hazard only) ----
#pragma unroll
        for (int nt = 0; nt < 4; ++nt) {
            *reinterpret_cast<float2*>(QP + (r0 + tq) * 68 + nt * 8 + 2 * tr) =
                make_float2(sacc[nt][0], sacc[nt][1]);
            *reinterpret_cast<float2*>(QP + (r0 + tq + 8) * 68 + nt * 8 + 2 * tr) =
                make_float2(sacc[nt][2], sacc[nt][3]);
        }
        __syncwarp();

        // ---- O += P V  (k-dim = 32), P fragments via ldmatrix ----
#pragma unroll
        for (int ks = 0; ks < 4; ++ks) {
            uint32_t af[4];
            ldsm4(af, sbase + poff + (uint32_t)(ks * 8 * 4));
#pragma unroll
            for (int nt = 0; nt < 8; ++nt) {
                const float* bp = Vs + (ks * 8 + tr) * 72 + nt * 8 + tq;
                uint32_t bf[2] = { __float_as_uint(bp[0]),
                                   __float_as_uint(bp[4 * 72]) };
                mma_tf32(oacc[nt], af, bf);
            }
        }
        // no end-of-loop sync: next iteration's single sync covers reuse
    }
#undef KV_LOAD

    // ---- normalize + write g_ao (tf32-rounded) ----
#pragma unroll
    for (int hh = 0; hh < 2; ++hh) {
        const int i = q0 + r0 + tq + 8 * hh;
        if (i < NN) {
            const float inv = 1.f / lrow_s[hh];
#pragma unroll
            for (int nt = 0; nt < 8; ++nt) {
                float2 w = make_float2(oacc[nt][2 * hh] * inv,
                                       oacc[nt][2 * hh + 1] * inv);
                w.x = rna_tf32(w.x); w.y = rna_tf32(w.y);
                *reinterpret_cast<float2*>(
                    g_ao + ((size_t)b * NN + i) * CC + h * HD + nt * 8 + 2 * tr) = w;
            }
        }
    }
}

// ---------------------------------------------------------------------------
extern "C" void kernel_launch(void* const* d_in, const int* in_sizes, int n_in,
                              void* d_out, int out_size)
{
    const float* x         = (const float*)d_in[0];
    const float* qkv_w     = (const float*)d_in[1];
    const float* proj_w    = (const float*)d_in[2];
    const float* proj_b    = (const float*)d_in[3];
    const float* rel_table = (const float*)d_in[4];
    const float* g2l       = (const float*)d_in[5];
    const float* g2g       = (const float*)d_in[6];
    float* out = (float*)d_out;

    (void)in_sizes; (void)n_in; (void)out_size;

    cudaFuncSetAttribute(attn_mma,
                         cudaFuncAttributeMaxDynamicSharedMemorySize, ATTN_SMEM);
    cudaFuncSetAttribute(gemm_mma<0>,
                         cudaFuncAttributeMaxDynamicSharedMemorySize, GEMM_SMEM);
    cudaFuncSetAttribute(gemm_mma<1>,
                         cudaFuncAttributeMaxDynamicSharedMemorySize, GEMM_SMEM);

    // 0) tf32 rounding (single launch) + bias precompute
    {
        int n4 = N4X + N4Q + N4P;
        round_all<<<(n4 + 255) / 256, 256>>>(x, qkv_w, proj_w);
        dim3 gb(HH, NN);
        bias_kernel<<<gb, 256>>>(rel_table, g2l, g2g);
    }
    // 1) QKV GEMM (tf32 mma.sync + ldmatrix)
    {
        dim3 grid(QKVN / 128, (MROWS + 127) / 128);   // (18, 99)
        gemm_mma<0><<<grid, 256, GEMM_SMEM>>>(nullptr, nullptr, MROWS);
    }
    // 2) flash attention (tf32 mma.sync + ldmatrix) -> g_ao
    {
        dim3 grid((NN + 127) / 128, BB * HH);         // (7, 192)
        attn_mma<<<grid, 256, ATTN_SMEM>>>();
    }
    // 3) proj GEMM (tf32 mma.sync + ldmatrix) + bias -> out
    {
        dim3 grid(CC / 128, (MROWS + 127) / 128);     // (6, 99)
        gemm_mma<1><<<grid, 256, GEMM_SMEM>>>(proj_b, out, MROWS);
    }
}